// round 1
// baseline (speedup 1.0000x reference)
#include <cuda_runtime.h>
#include <cuda_bf16.h>
#include <cstdint>

// Problem constants
#define B_  16
#define S_  1024
#define T_  512
#define D_  512
#define H_  8
#define DH_ 64
#define DF_ 2048
#define E_  4
#define BSROWS (B_*S_)    // 16384
#define BTROWS (B_*T_)    // 8192
#define EPS_ 1e-5f

// ---------------- scratch (static __device__ — no allocation) ----------------
__device__ float g_q  [BSROWS*D_];
__device__ float g_k  [BSROWS*D_];
__device__ float g_v  [BSROWS*D_];
__device__ float g_att[BSROWS*D_];
__device__ float g_pre[BSROWS*D_];
__device__ float g_xa [BSROWS*D_];
__device__ float g_xb [BSROWS*D_];
__device__ float g_y  [BSROWS*D_];
__device__ float g_h  [BSROWS*DF_];
__device__ float g_gates[BSROWS*E_];
__device__ float g_gsum[E_];

// ---------------- tiny utility kernels ----------------
__global__ void zero_gsum_kernel() {
    if (threadIdx.x < E_) g_gsum[threadIdx.x] = 0.f;
}

__global__ void aux_kernel(float* out, int out_size) {
    float s = 0.f;
#pragma unroll
    for (int e = 0; e < E_; e++) {
        float mn = g_gsum[e] * (1.f / (float)BSROWS);
        s += mn * mn;
    }
    if (out_size > BSROWS * D_) out[BSROWS * D_] = (float)E_ * s;
}

// ---------------- generic SGEMM with fused epilogue ----------------
// C[M,N] = epilogue(A[M,K] @ W[K,N] + bias)
// flags: 1 = relu, 2 = accumulate into C
// rowscale (optional): v *= rowscale[m*rs_stride]
// res (optional): v += res[m*N + n]
#define FLAG_RELU  1
#define FLAG_ACCUM 2

__global__ void __launch_bounds__(256)
sgemm_kernel(const float* __restrict__ A, const float* __restrict__ W,
             const float* __restrict__ bias,
             const float* __restrict__ res,
             const float* __restrict__ rowscale, int rs_stride,
             float* __restrict__ C,
             int M, int N, int K, int flags)
{
    constexpr int BM = 128, BN = 128, BK = 8;
    __shared__ float As[BK][BM];
    __shared__ float Ws[BK][BN];

    const int tid = threadIdx.x;
    const int m0 = blockIdx.y * BM, n0 = blockIdx.x * BN;
    const int tx = tid & 15, ty = tid >> 4;

    float acc[8][8];
#pragma unroll
    for (int i = 0; i < 8; i++)
#pragma unroll
        for (int j = 0; j < 8; j++) acc[i][j] = 0.f;

    const int arow = tid >> 1;           // 0..127
    const int acol = (tid & 1) * 4;      // 0 or 4
    const int wrow = tid >> 5;           // 0..7
    const int wcol = (tid & 31) * 4;     // 0..124

    const float* Aptr = A + (size_t)(m0 + arow) * K + acol;
    const float* Wptr = W + (size_t)wrow * N + (n0 + wcol);

    for (int k0 = 0; k0 < K; k0 += BK) {
        float4 av = *(const float4*)(Aptr + k0);
        As[acol + 0][arow] = av.x;
        As[acol + 1][arow] = av.y;
        As[acol + 2][arow] = av.z;
        As[acol + 3][arow] = av.w;
        float4 wv = *(const float4*)(Wptr + (size_t)k0 * N);
        *(float4*)&Ws[wrow][wcol] = wv;
        __syncthreads();

#pragma unroll
        for (int kk = 0; kk < BK; kk++) {
            float4 a0 = *(const float4*)&As[kk][ty * 8];
            float4 a1 = *(const float4*)&As[kk][ty * 8 + 4];
            float4 b0 = *(const float4*)&Ws[kk][tx * 8];
            float4 b1 = *(const float4*)&Ws[kk][tx * 8 + 4];
            float ar[8] = {a0.x, a0.y, a0.z, a0.w, a1.x, a1.y, a1.z, a1.w};
            float br[8] = {b0.x, b0.y, b0.z, b0.w, b1.x, b1.y, b1.z, b1.w};
#pragma unroll
            for (int i = 0; i < 8; i++)
#pragma unroll
                for (int j = 0; j < 8; j++)
                    acc[i][j] += ar[i] * br[j];
        }
        __syncthreads();
    }

    const bool do_relu  = (flags & FLAG_RELU)  != 0;
    const bool do_accum = (flags & FLAG_ACCUM) != 0;
#pragma unroll
    for (int i = 0; i < 8; i++) {
        int m = m0 + ty * 8 + i;
        float rsv = rowscale ? rowscale[(size_t)m * rs_stride] : 1.f;
        size_t rowoff = (size_t)m * N + n0 + tx * 8;
#pragma unroll
        for (int j = 0; j < 8; j++) {
            float v = acc[i][j] + (bias ? bias[n0 + tx * 8 + j] : 0.f);
            if (do_relu) v = fmaxf(v, 0.f);
            v *= rsv;
            if (res)      v += res[rowoff + j];
            if (do_accum) v += C[rowoff + j];
            C[rowoff + j] = v;
        }
    }
}

static inline void gemm(const float* A, const float* W, const float* bias,
                        const float* res, const float* rs, int rss,
                        float* C, int M, int N, int K, int flags)
{
    dim3 grid(N / 128, M / 128);
    sgemm_kernel<<<grid, 256>>>(A, W, bias, res, rs, rss, C, M, N, K, flags);
}

// ---------------- flash attention (fp32, online softmax) ----------------
// Q has B*S rows; K/V have B*Sk rows. Head h occupies columns [h*64, h*64+64).
// grid: (S/64, H, B), block: 64 threads (1 thread per query row).
template<bool CAUSAL>
__global__ void __launch_bounds__(64)
attn_kernel(const float* __restrict__ Q, const float* __restrict__ K,
            const float* __restrict__ V, float* __restrict__ O, int Sk)
{
    __shared__ float Ks[64][65];
    __shared__ float Vs[64][65];
    const int b = blockIdx.z, h = blockIdx.y, qt = blockIdx.x;
    const int t = threadIdx.x;
    const int qrow = qt * 64 + t;

    const float* qptr = Q + ((size_t)b * S_ + qrow) * D_ + h * DH_;
    float q[64];
#pragma unroll
    for (int d = 0; d < 64; d++) q[d] = qptr[d] * 0.125f;  // 1/sqrt(64)

    float o[64];
#pragma unroll
    for (int d = 0; d < 64; d++) o[d] = 0.f;
    float m = -1e30f, l = 0.f;

    const int ntiles = CAUSAL ? (qt + 1) : (Sk >> 6);
    for (int kt = 0; kt < ntiles; kt++) {
        const float* kbase = K + ((size_t)b * Sk + kt * 64) * D_ + h * DH_;
        const float* vbase = V + ((size_t)b * Sk + kt * 64) * D_ + h * DH_;
#pragma unroll 8
        for (int i = 0; i < 64; i++) {
            Ks[i][t] = kbase[(size_t)i * D_ + t];
            Vs[i][t] = vbase[(size_t)i * D_ + t];
        }
        __syncthreads();

#pragma unroll
        for (int c = 0; c < 2; c++) {
            float s[32];
            float tmax = -1e30f;
#pragma unroll
            for (int j = 0; j < 32; j++) {
                const int jj = c * 32 + j;
                float a = 0.f;
#pragma unroll
                for (int d = 0; d < 64; d++) a += q[d] * Ks[jj][d];
                if (CAUSAL && (kt * 64 + jj) > qrow) a = -1e30f;
                s[j] = a;
                tmax = fmaxf(tmax, a);
            }
            float mnew = fmaxf(m, tmax);
            float corr = __expf(m - mnew);
            l *= corr;
#pragma unroll
            for (int d = 0; d < 64; d++) o[d] *= corr;
#pragma unroll
            for (int j = 0; j < 32; j++) {
                float p = __expf(s[j] - mnew);
                l += p;
                const int jj = c * 32 + j;
#pragma unroll
                for (int d = 0; d < 64; d++) o[d] += p * Vs[jj][d];
            }
            m = mnew;
        }
        __syncthreads();
    }

    float inv = 1.f / l;
    float* optr = O + ((size_t)b * S_ + qrow) * D_ + h * DH_;
#pragma unroll
    for (int d = 0; d < 64; d++) optr[d] = o[d] * inv;
}

// ---------------- LayerNorm: out = LN(a + b?) * g + beta ----------------
// grid: 16384 blocks (one per row), 256 threads.
__global__ void __launch_bounds__(256)
ln_kernel(const float* __restrict__ a, const float* __restrict__ b,
          const float* __restrict__ g, const float* __restrict__ be,
          float* __restrict__ out)
{
    const int row = blockIdx.x;
    const int t = threadIdx.x;
    const size_t base = (size_t)row * D_;
    float v0 = a[base + t];
    float v1 = a[base + t + 256];
    if (b) { v0 += b[base + t]; v1 += b[base + t + 256]; }

    float s = v0 + v1, ss = v0 * v0 + v1 * v1;
    const int lane = t & 31, w = t >> 5;
    __shared__ float shs[8], shss[8];
#pragma unroll
    for (int off = 16; off; off >>= 1) {
        s  += __shfl_down_sync(0xffffffffu, s,  off);
        ss += __shfl_down_sync(0xffffffffu, ss, off);
    }
    if (lane == 0) { shs[w] = s; shss[w] = ss; }
    __syncthreads();
    __shared__ float mean_sh, inv_sh;
    if (t == 0) {
        float S = 0.f, SS = 0.f;
#pragma unroll
        for (int i = 0; i < 8; i++) { S += shs[i]; SS += shss[i]; }
        float mean = S * (1.f / (float)D_);
        float var  = SS * (1.f / (float)D_) - mean * mean;
        mean_sh = mean;
        inv_sh  = rsqrtf(var + EPS_);
    }
    __syncthreads();
    float mean = mean_sh, inv = inv_sh;
    out[base + t]       = (v0 - mean) * inv * g[t]       + be[t];
    out[base + t + 256] = (v1 - mean) * inv * g[t + 256] + be[t + 256];
}

// ---------------- gate: softmax(x @ gw + gb) + per-expert sums ----------------
// one warp per row
__global__ void __launch_bounds__(256)
gate_kernel(const float* __restrict__ x, const float* __restrict__ gw,
            const float* __restrict__ gb)
{
    const int warp = (blockIdx.x * blockDim.x + threadIdx.x) >> 5;
    const int lane = threadIdx.x & 31;
    if (warp >= BSROWS) return;
    const float* xr = x + (size_t)warp * D_;
    float a0 = 0.f, a1 = 0.f, a2 = 0.f, a3 = 0.f;
    for (int d = lane; d < D_; d += 32) {
        float xv = xr[d];
        const float* wr = gw + (size_t)d * E_;
        a0 += xv * wr[0]; a1 += xv * wr[1]; a2 += xv * wr[2]; a3 += xv * wr[3];
    }
#pragma unroll
    for (int off = 16; off; off >>= 1) {
        a0 += __shfl_down_sync(0xffffffffu, a0, off);
        a1 += __shfl_down_sync(0xffffffffu, a1, off);
        a2 += __shfl_down_sync(0xffffffffu, a2, off);
        a3 += __shfl_down_sync(0xffffffffu, a3, off);
    }
    if (lane == 0) {
        float l0 = a0 + gb[0], l1 = a1 + gb[1], l2 = a2 + gb[2], l3 = a3 + gb[3];
        float mx = fmaxf(fmaxf(l0, l1), fmaxf(l2, l3));
        float e0 = __expf(l0 - mx), e1 = __expf(l1 - mx);
        float e2 = __expf(l2 - mx), e3 = __expf(l3 - mx);
        float si = 1.f / (e0 + e1 + e2 + e3);
        float p0 = e0 * si, p1 = e1 * si, p2 = e2 * si, p3 = e3 * si;
        float* gp = g_gates + (size_t)warp * E_;
        gp[0] = p0; gp[1] = p1; gp[2] = p2; gp[3] = p3;
        atomicAdd(&g_gsum[0], p0);
        atomicAdd(&g_gsum[1], p1);
        atomicAdd(&g_gsum[2], p2);
        atomicAdd(&g_gsum[3], p3);
    }
}

// ---------------- host orchestration ----------------
extern "C" void kernel_launch(void* const* d_in, const int* in_sizes, int n_in,
                              void* d_out, int out_size)
{
    const float* x      = (const float*)d_in[0];
    const float* cross  = (const float*)d_in[1];
    const float* sa_wq  = (const float*)d_in[2];
    const float* sa_bq  = (const float*)d_in[3];
    const float* sa_wk  = (const float*)d_in[4];
    const float* sa_bk  = (const float*)d_in[5];
    const float* sa_wv  = (const float*)d_in[6];
    const float* sa_bv  = (const float*)d_in[7];
    const float* sa_wo  = (const float*)d_in[8];
    const float* sa_bo  = (const float*)d_in[9];
    const float* ca_wq  = (const float*)d_in[10];
    const float* ca_bq  = (const float*)d_in[11];
    const float* ca_wk  = (const float*)d_in[12];
    const float* ca_bk  = (const float*)d_in[13];
    const float* ca_wv  = (const float*)d_in[14];
    const float* ca_bv  = (const float*)d_in[15];
    const float* ca_wo  = (const float*)d_in[16];
    const float* ca_bo  = (const float*)d_in[17];
    const float* gate_w = (const float*)d_in[18];
    const float* gate_b = (const float*)d_in[19];
    const float* exp_w1 = (const float*)d_in[20];
    const float* exp_b1 = (const float*)d_in[21];
    const float* exp_w2 = (const float*)d_in[22];
    const float* exp_b2 = (const float*)d_in[23];
    const float* n1_g   = (const float*)d_in[24];
    const float* n1_b   = (const float*)d_in[25];
    const float* n2_g   = (const float*)d_in[26];
    const float* n2_b   = (const float*)d_in[27];
    const float* n3_g   = (const float*)d_in[28];
    const float* n3_b   = (const float*)d_in[29];
    float* out = (float*)d_out;

    float *q, *k, *v, *att, *pre, *xa, *xb, *y, *h, *gates;
    cudaGetSymbolAddress((void**)&q,    g_q);
    cudaGetSymbolAddress((void**)&k,    g_k);
    cudaGetSymbolAddress((void**)&v,    g_v);
    cudaGetSymbolAddress((void**)&att,  g_att);
    cudaGetSymbolAddress((void**)&pre,  g_pre);
    cudaGetSymbolAddress((void**)&xa,   g_xa);
    cudaGetSymbolAddress((void**)&xb,   g_xb);
    cudaGetSymbolAddress((void**)&y,    g_y);
    cudaGetSymbolAddress((void**)&h,    g_h);
    cudaGetSymbolAddress((void**)&gates, g_gates);

    zero_gsum_kernel<<<1, 32>>>();

    // ---- self-attention block ----
    gemm(x, sa_wq, sa_bq, nullptr, nullptr, 0, q, BSROWS, D_, D_, 0);
    gemm(x, sa_wk, sa_bk, nullptr, nullptr, 0, k, BSROWS, D_, D_, 0);
    gemm(x, sa_wv, sa_bv, nullptr, nullptr, 0, v, BSROWS, D_, D_, 0);
    attn_kernel<true><<<dim3(S_ / 64, H_, B_), 64>>>(q, k, v, att, S_);
    gemm(att, sa_wo, sa_bo, /*res=*/x, nullptr, 0, pre, BSROWS, D_, D_, 0);
    ln_kernel<<<BSROWS, 256>>>(pre, nullptr, n1_g, n1_b, xa);

    // ---- cross-attention block ----
    gemm(xa,    ca_wq, ca_bq, nullptr, nullptr, 0, q, BSROWS, D_, D_, 0);
    gemm(cross, ca_wk, ca_bk, nullptr, nullptr, 0, k, BTROWS, D_, D_, 0);
    gemm(cross, ca_wv, ca_bv, nullptr, nullptr, 0, v, BTROWS, D_, D_, 0);
    attn_kernel<false><<<dim3(S_ / 64, H_, B_), 64>>>(q, k, v, att, T_);
    gemm(att, ca_wo, ca_bo, /*res=*/xa, nullptr, 0, pre, BSROWS, D_, D_, 0);
    ln_kernel<<<BSROWS, 256>>>(pre, nullptr, n2_g, n2_b, xb);

    // ---- MoE ----
    gate_kernel<<<(BSROWS * 32 + 255) / 256, 256>>>(xb, gate_w, gate_b);
    aux_kernel<<<1, 1>>>(out, out_size);
    for (int e = 0; e < E_; e++) {
        gemm(xb, exp_w1 + (size_t)e * D_ * DF_, exp_b1 + (size_t)e * DF_,
             nullptr, nullptr, 0, h, BSROWS, DF_, D_, FLAG_RELU);
        gemm(h, exp_w2 + (size_t)e * DF_ * D_, exp_b2 + (size_t)e * D_,
             nullptr, gates + e, E_, y, BSROWS, D_, DF_, e ? FLAG_ACCUM : 0);
    }
    ln_kernel<<<BSROWS, 256>>>(xb, y, n3_g, n3_b, out);
}

// round 2
// speedup vs baseline: 2.2283x; 2.2283x over previous
#include <cuda_runtime.h>
#include <cuda_bf16.h>
#include <cstdint>

// Problem constants
#define B_  16
#define S_  1024
#define T_  512
#define D_  512
#define H_  8
#define DH_ 64
#define DF_ 2048
#define E_  4
#define BSROWS (B_*S_)    // 16384
#define BTROWS (B_*T_)    // 8192
#define EPS_ 1e-5f

// ---------------- scratch (static __device__ — no allocation) ----------------
__device__ float g_q  [BSROWS*D_];
__device__ float g_k  [BSROWS*D_];
__device__ float g_v  [BSROWS*D_];
__device__ float g_att[BSROWS*D_];
__device__ float g_pre[BSROWS*D_];
__device__ float g_xa [BSROWS*D_];
__device__ float g_xb [BSROWS*D_];
__device__ float g_y  [BSROWS*D_];
__device__ float g_h  [BSROWS*DF_];
__device__ float g_gates[BSROWS*E_];
__device__ float g_gsum[E_];

// ---------------- tiny utility kernels ----------------
__global__ void zero_gsum_kernel() {
    if (threadIdx.x < E_) g_gsum[threadIdx.x] = 0.f;
}

__global__ void aux_kernel(float* out, int out_size) {
    float s = 0.f;
#pragma unroll
    for (int e = 0; e < E_; e++) {
        float mn = g_gsum[e] * (1.f / (float)BSROWS);
        s += mn * mn;
    }
    if (out_size > BSROWS * D_) out[BSROWS * D_] = (float)E_ * s;
}

// ---------------- helpers ----------------
__device__ __forceinline__ uint32_t f2tf32(float f) {
    uint32_t u;
    asm volatile("cvt.rna.tf32.f32 %0, %1;\n" : "=r"(u) : "f"(f));
    return u;
}

__device__ __forceinline__ void cp16(void* smem, const void* gmem) {
    uint32_t s = (uint32_t)__cvta_generic_to_shared(smem);
    asm volatile("cp.async.cg.shared.global [%0], [%1], 16;\n" :: "r"(s), "l"(gmem));
}
__device__ __forceinline__ void cp_commit() { asm volatile("cp.async.commit_group;\n"); }
__device__ __forceinline__ void cp_wait0()  { asm volatile("cp.async.wait_group 0;\n"); }

__device__ __forceinline__ void mma_tf32(float c[4], const uint32_t a[4], const uint32_t b[2]) {
    asm volatile(
        "mma.sync.aligned.m16n8k8.row.col.f32.tf32.tf32.f32 "
        "{%0,%1,%2,%3}, {%4,%5,%6,%7}, {%8,%9}, {%0,%1,%2,%3};\n"
        : "+f"(c[0]), "+f"(c[1]), "+f"(c[2]), "+f"(c[3])
        : "r"(a[0]), "r"(a[1]), "r"(a[2]), "r"(a[3]), "r"(b[0]), "r"(b[1]));
}

// ---------------- TF32 tensor-core GEMM with fused epilogue ----------------
// C[M,N] = epilogue(A[M,K] @ W[K,N] + bias)
// flags: 1 = relu, 2 = accumulate into C
// rowscale (optional): v *= rowscale[m*rs_stride]
// res (optional): v += res[m*N + n]
#define FLAG_RELU  1
#define FLAG_ACCUM 2

// Block tile 128x128x16, 256 threads = 8 warps (2 x 4), warp tile 64x32.
// Each warp: 4x4 grid of m16n8k8 mma.
__global__ void __launch_bounds__(256)
tgemm_kernel(const float* __restrict__ A, const float* __restrict__ W,
             const float* __restrict__ bias,
             const float* __restrict__ res,
             const float* __restrict__ rowscale, int rs_stride,
             float* __restrict__ C,
             int M, int N, int K, int flags)
{
    constexpr int BM = 128, BN = 128, BK = 16;
    constexpr int ASTR = 20;   // pad: conflict-free fragment gather
    constexpr int BSTR = 136;  // pad: conflict-free fragment gather
    __shared__ float As[2][BM][ASTR];
    __shared__ float Bs[2][BK][BSTR];

    const int tid  = threadIdx.x;
    const int warp = tid >> 5;
    const int lane = tid & 31;
    const int r = lane >> 2;     // 0..7
    const int c = lane & 3;      // 0..3
    const int wm = warp >> 2;    // 0..1
    const int wn = warp & 3;     // 0..3
    const int m0 = blockIdx.y * BM, n0 = blockIdx.x * BN;

    float acc[4][4][4];
#pragma unroll
    for (int i = 0; i < 4; i++)
#pragma unroll
        for (int j = 0; j < 4; j++)
#pragma unroll
            for (int q = 0; q < 4; q++) acc[i][j][q] = 0.f;

    // global load mapping
    const int a_row = tid >> 2;            // 0..63 (and +64)
    const int a_c4  = (tid & 3) * 4;       // 0,4,8,12
    const int b_row = tid >> 5;            // 0..7 (and +8)
    const int b_c4  = (tid & 31) * 4;      // 0..124

    const float* Ag = A + (size_t)(m0 + a_row) * K + a_c4;
    const float* Bg = W + (size_t)b_row * N + n0 + b_c4;

    const int ntiles = K / BK;

    // prologue: stage 0
    {
        cp16(&As[0][a_row][a_c4],      Ag);
        cp16(&As[0][a_row + 64][a_c4], Ag + (size_t)64 * K);
        cp16(&Bs[0][b_row][b_c4],      Bg);
        cp16(&Bs[0][b_row + 8][b_c4],  Bg + (size_t)8 * N);
        cp_commit();
    }

    for (int t = 0; t < ntiles; t++) {
        cp_wait0();
        __syncthreads();
        const int cur = t & 1;
        if (t + 1 < ntiles) {
            const int nxt = cur ^ 1;
            const float* Agn = Ag + (size_t)(t + 1) * BK;
            const float* Bgn = Bg + (size_t)(t + 1) * BK * N;
            cp16(&As[nxt][a_row][a_c4],      Agn);
            cp16(&As[nxt][a_row + 64][a_c4], Agn + (size_t)64 * K);
            cp16(&Bs[nxt][b_row][b_c4],      Bgn);
            cp16(&Bs[nxt][b_row + 8][b_c4],  Bgn + (size_t)8 * N);
            cp_commit();
        }

#pragma unroll
        for (int ks = 0; ks < 2; ks++) {
            const int kk = ks * 8;
            uint32_t af[4][4];
            uint32_t bf[4][2];
#pragma unroll
            for (int mi = 0; mi < 4; mi++) {
                const int m = wm * 64 + mi * 16;
                af[mi][0] = f2tf32(As[cur][m + r][kk + c]);
                af[mi][1] = f2tf32(As[cur][m + r + 8][kk + c]);
                af[mi][2] = f2tf32(As[cur][m + r][kk + c + 4]);
                af[mi][3] = f2tf32(As[cur][m + r + 8][kk + c + 4]);
            }
#pragma unroll
            for (int nj = 0; nj < 4; nj++) {
                const int n = wn * 32 + nj * 8 + r;
                bf[nj][0] = f2tf32(Bs[cur][kk + c][n]);
                bf[nj][1] = f2tf32(Bs[cur][kk + c + 4][n]);
            }
#pragma unroll
            for (int mi = 0; mi < 4; mi++)
#pragma unroll
                for (int nj = 0; nj < 4; nj++)
                    mma_tf32(acc[mi][nj], af[mi], bf[nj]);
        }
        // next-iteration top barrier protects smem reuse
    }

    // ---------------- epilogue ----------------
    const bool do_relu  = (flags & FLAG_RELU)  != 0;
    const bool do_accum = (flags & FLAG_ACCUM) != 0;
#pragma unroll
    for (int mi = 0; mi < 4; mi++) {
        const int mrow0 = m0 + wm * 64 + mi * 16 + r;
#pragma unroll
        for (int half = 0; half < 2; half++) {
            const int mrow = mrow0 + half * 8;
            const float rsv = rowscale ? rowscale[(size_t)mrow * rs_stride] : 1.f;
            const size_t rowbase = (size_t)mrow * N;
#pragma unroll
            for (int nj = 0; nj < 4; nj++) {
                const int ncol = n0 + wn * 32 + nj * 8 + 2 * c;
                float v0 = acc[mi][nj][half * 2 + 0];
                float v1 = acc[mi][nj][half * 2 + 1];
                if (bias) { v0 += bias[ncol]; v1 += bias[ncol + 1]; }
                if (do_relu) { v0 = fmaxf(v0, 0.f); v1 = fmaxf(v1, 0.f); }
                v0 *= rsv; v1 *= rsv;
                if (res) { v0 += res[rowbase + ncol]; v1 += res[rowbase + ncol + 1]; }
                if (do_accum) { v0 += C[rowbase + ncol]; v1 += C[rowbase + ncol + 1]; }
                *(float2*)&C[rowbase + ncol] = make_float2(v0, v1);
            }
        }
    }
}

static inline void gemm(const float* A, const float* W, const float* bias,
                        const float* res, const float* rs, int rss,
                        float* C, int M, int N, int K, int flags)
{
    dim3 grid(N / 128, M / 128);
    tgemm_kernel<<<grid, 256>>>(A, W, bias, res, rs, rss, C, M, N, K, flags);
}

// ---------------- flash attention (fp32, online softmax) ----------------
// Q has B*S rows; K/V have B*Sk rows. Head h occupies columns [h*64, h*64+64).
// grid: (S/64, H, B), block: 64 threads (1 thread per query row).
template<bool CAUSAL>
__global__ void __launch_bounds__(64)
attn_kernel(const float* __restrict__ Q, const float* __restrict__ K,
            const float* __restrict__ V, float* __restrict__ O, int Sk)
{
    __shared__ float Ks[64][65];
    __shared__ float Vs[64][65];
    const int b = blockIdx.z, h = blockIdx.y, qt = blockIdx.x;
    const int t = threadIdx.x;
    const int qrow = qt * 64 + t;

    const float* qptr = Q + ((size_t)b * S_ + qrow) * D_ + h * DH_;
    float q[64];
#pragma unroll
    for (int d = 0; d < 64; d++) q[d] = qptr[d] * 0.125f;  // 1/sqrt(64)

    float o[64];
#pragma unroll
    for (int d = 0; d < 64; d++) o[d] = 0.f;
    float m = -1e30f, l = 0.f;

    const int ntiles = CAUSAL ? (qt + 1) : (Sk >> 6);
    for (int kt = 0; kt < ntiles; kt++) {
        const float* kbase = K + ((size_t)b * Sk + kt * 64) * D_ + h * DH_;
        const float* vbase = V + ((size_t)b * Sk + kt * 64) * D_ + h * DH_;
#pragma unroll 8
        for (int i = 0; i < 64; i++) {
            Ks[i][t] = kbase[(size_t)i * D_ + t];
            Vs[i][t] = vbase[(size_t)i * D_ + t];
        }
        __syncthreads();

#pragma unroll
        for (int c = 0; c < 2; c++) {
            float s[32];
            float tmax = -1e30f;
#pragma unroll
            for (int j = 0; j < 32; j++) {
                const int jj = c * 32 + j;
                float a = 0.f;
#pragma unroll
                for (int d = 0; d < 64; d++) a += q[d] * Ks[jj][d];
                if (CAUSAL && (kt * 64 + jj) > qrow) a = -1e30f;
                s[j] = a;
                tmax = fmaxf(tmax, a);
            }
            float mnew = fmaxf(m, tmax);
            float corr = __expf(m - mnew);
            l *= corr;
#pragma unroll
            for (int d = 0; d < 64; d++) o[d] *= corr;
#pragma unroll
            for (int j = 0; j < 32; j++) {
                float p = __expf(s[j] - mnew);
                l += p;
                const int jj = c * 32 + j;
#pragma unroll
                for (int d = 0; d < 64; d++) o[d] += p * Vs[jj][d];
            }
            m = mnew;
        }
        __syncthreads();
    }

    float inv = 1.f / l;
    float* optr = O + ((size_t)b * S_ + qrow) * D_ + h * DH_;
#pragma unroll
    for (int d = 0; d < 64; d++) optr[d] = o[d] * inv;
}

// ---------------- LayerNorm: out = LN(a + b?) * g + beta ----------------
__global__ void __launch_bounds__(256)
ln_kernel(const float* __restrict__ a, const float* __restrict__ b,
          const float* __restrict__ g, const float* __restrict__ be,
          float* __restrict__ out)
{
    const int row = blockIdx.x;
    const int t = threadIdx.x;
    const size_t base = (size_t)row * D_;
    float v0 = a[base + t];
    float v1 = a[base + t + 256];
    if (b) { v0 += b[base + t]; v1 += b[base + t + 256]; }

    float s = v0 + v1, ss = v0 * v0 + v1 * v1;
    const int lane = t & 31, w = t >> 5;
    __shared__ float shs[8], shss[8];
#pragma unroll
    for (int off = 16; off; off >>= 1) {
        s  += __shfl_down_sync(0xffffffffu, s,  off);
        ss += __shfl_down_sync(0xffffffffu, ss, off);
    }
    if (lane == 0) { shs[w] = s; shss[w] = ss; }
    __syncthreads();
    __shared__ float mean_sh, inv_sh;
    if (t == 0) {
        float S = 0.f, SS = 0.f;
#pragma unroll
        for (int i = 0; i < 8; i++) { S += shs[i]; SS += shss[i]; }
        float mean = S * (1.f / (float)D_);
        float var  = SS * (1.f / (float)D_) - mean * mean;
        mean_sh = mean;
        inv_sh  = rsqrtf(var + EPS_);
    }
    __syncthreads();
    float mean = mean_sh, inv = inv_sh;
    out[base + t]       = (v0 - mean) * inv * g[t]       + be[t];
    out[base + t + 256] = (v1 - mean) * inv * g[t + 256] + be[t + 256];
}

// ---------------- gate: softmax(x @ gw + gb) + per-expert sums ----------------
__global__ void __launch_bounds__(256)
gate_kernel(const float* __restrict__ x, const float* __restrict__ gw,
            const float* __restrict__ gb)
{
    const int warp = (blockIdx.x * blockDim.x + threadIdx.x) >> 5;
    const int lane = threadIdx.x & 31;
    if (warp >= BSROWS) return;
    const float* xr = x + (size_t)warp * D_;
    float a0 = 0.f, a1 = 0.f, a2 = 0.f, a3 = 0.f;
    for (int d = lane; d < D_; d += 32) {
        float xv = xr[d];
        const float* wr = gw + (size_t)d * E_;
        a0 += xv * wr[0]; a1 += xv * wr[1]; a2 += xv * wr[2]; a3 += xv * wr[3];
    }
#pragma unroll
    for (int off = 16; off; off >>= 1) {
        a0 += __shfl_down_sync(0xffffffffu, a0, off);
        a1 += __shfl_down_sync(0xffffffffu, a1, off);
        a2 += __shfl_down_sync(0xffffffffu, a2, off);
        a3 += __shfl_down_sync(0xffffffffu, a3, off);
    }
    if (lane == 0) {
        float l0 = a0 + gb[0], l1 = a1 + gb[1], l2 = a2 + gb[2], l3 = a3 + gb[3];
        float mx = fmaxf(fmaxf(l0, l1), fmaxf(l2, l3));
        float e0 = __expf(l0 - mx), e1 = __expf(l1 - mx);
        float e2 = __expf(l2 - mx), e3 = __expf(l3 - mx);
        float si = 1.f / (e0 + e1 + e2 + e3);
        float p0 = e0 * si, p1 = e1 * si, p2 = e2 * si, p3 = e3 * si;
        float* gp = g_gates + (size_t)warp * E_;
        gp[0] = p0; gp[1] = p1; gp[2] = p2; gp[3] = p3;
        atomicAdd(&g_gsum[0], p0);
        atomicAdd(&g_gsum[1], p1);
        atomicAdd(&g_gsum[2], p2);
        atomicAdd(&g_gsum[3], p3);
    }
}

// ---------------- host orchestration ----------------
extern "C" void kernel_launch(void* const* d_in, const int* in_sizes, int n_in,
                              void* d_out, int out_size)
{
    const float* x      = (const float*)d_in[0];
    const float* cross  = (const float*)d_in[1];
    const float* sa_wq  = (const float*)d_in[2];
    const float* sa_bq  = (const float*)d_in[3];
    const float* sa_wk  = (const float*)d_in[4];
    const float* sa_bk  = (const float*)d_in[5];
    const float* sa_wv  = (const float*)d_in[6];
    const float* sa_bv  = (const float*)d_in[7];
    const float* sa_wo  = (const float*)d_in[8];
    const float* sa_bo  = (const float*)d_in[9];
    const float* ca_wq  = (const float*)d_in[10];
    const float* ca_bq  = (const float*)d_in[11];
    const float* ca_wk  = (const float*)d_in[12];
    const float* ca_bk  = (const float*)d_in[13];
    const float* ca_wv  = (const float*)d_in[14];
    const float* ca_bv  = (const float*)d_in[15];
    const float* ca_wo  = (const float*)d_in[16];
    const float* ca_bo  = (const float*)d_in[17];
    const float* gate_w = (const float*)d_in[18];
    const float* gate_b = (const float*)d_in[19];
    const float* exp_w1 = (const float*)d_in[20];
    const float* exp_b1 = (const float*)d_in[21];
    const float* exp_w2 = (const float*)d_in[22];
    const float* exp_b2 = (const float*)d_in[23];
    const float* n1_g   = (const float*)d_in[24];
    const float* n1_b   = (const float*)d_in[25];
    const float* n2_g   = (const float*)d_in[26];
    const float* n2_b   = (const float*)d_in[27];
    const float* n3_g   = (const float*)d_in[28];
    const float* n3_b   = (const float*)d_in[29];
    float* out = (float*)d_out;

    float *q, *k, *v, *att, *pre, *xa, *xb, *y, *h, *gates;
    cudaGetSymbolAddress((void**)&q,    g_q);
    cudaGetSymbolAddress((void**)&k,    g_k);
    cudaGetSymbolAddress((void**)&v,    g_v);
    cudaGetSymbolAddress((void**)&att,  g_att);
    cudaGetSymbolAddress((void**)&pre,  g_pre);
    cudaGetSymbolAddress((void**)&xa,   g_xa);
    cudaGetSymbolAddress((void**)&xb,   g_xb);
    cudaGetSymbolAddress((void**)&y,    g_y);
    cudaGetSymbolAddress((void**)&h,    g_h);
    cudaGetSymbolAddress((void**)&gates, g_gates);

    zero_gsum_kernel<<<1, 32>>>();

    // ---- self-attention block ----
    gemm(x, sa_wq, sa_bq, nullptr, nullptr, 0, q, BSROWS, D_, D_, 0);
    gemm(x, sa_wk, sa_bk, nullptr, nullptr, 0, k, BSROWS, D_, D_, 0);
    gemm(x, sa_wv, sa_bv, nullptr, nullptr, 0, v, BSROWS, D_, D_, 0);
    attn_kernel<true><<<dim3(S_ / 64, H_, B_), 64>>>(q, k, v, att, S_);
    gemm(att, sa_wo, sa_bo, /*res=*/x, nullptr, 0, pre, BSROWS, D_, D_, 0);
    ln_kernel<<<BSROWS, 256>>>(pre, nullptr, n1_g, n1_b, xa);

    // ---- cross-attention block ----
    gemm(xa,    ca_wq, ca_bq, nullptr, nullptr, 0, q, BSROWS, D_, D_, 0);
    gemm(cross, ca_wk, ca_bk, nullptr, nullptr, 0, k, BTROWS, D_, D_, 0);
    gemm(cross, ca_wv, ca_bv, nullptr, nullptr, 0, v, BTROWS, D_, D_, 0);
    attn_kernel<false><<<dim3(S_ / 64, H_, B_), 64>>>(q, k, v, att, T_);
    gemm(att, ca_wo, ca_bo, /*res=*/xa, nullptr, 0, pre, BSROWS, D_, D_, 0);
    ln_kernel<<<BSROWS, 256>>>(pre, nullptr, n2_g, n2_b, xb);

    // ---- MoE ----
    gate_kernel<<<(BSROWS * 32 + 255) / 256, 256>>>(xb, gate_w, gate_b);
    aux_kernel<<<1, 1>>>(out, out_size);
    for (int e = 0; e < E_; e++) {
        gemm(xb, exp_w1 + (size_t)e * D_ * DF_, exp_b1 + (size_t)e * DF_,
             nullptr, nullptr, 0, h, BSROWS, DF_, D_, FLAG_RELU);
        gemm(h, exp_w2 + (size_t)e * DF_ * D_, exp_b2 + (size_t)e * D_,
             nullptr, gates + e, E_, y, BSROWS, D_, DF_, e ? FLAG_ACCUM : 0);
    }
    ln_kernel<<<BSROWS, 256>>>(xb, y, n3_g, n3_b, out);
}

// round 3
// speedup vs baseline: 3.3517x; 1.5042x over previous
#include <cuda_runtime.h>
#include <cuda_bf16.h>
#include <cstdint>

// Problem constants
#define B_  16
#define S_  1024
#define T_  512
#define D_  512
#define H_  8
#define DH_ 64
#define DF_ 2048
#define E_  4
#define BSROWS (B_*S_)    // 16384
#define BTROWS (B_*T_)    // 8192
#define EPS_ 1e-5f

// ---------------- scratch (static __device__ — no allocation) ----------------
__device__ float g_q  [BSROWS*D_];
__device__ float g_k  [BSROWS*D_];
__device__ float g_v  [BSROWS*D_];
__device__ float g_att[BSROWS*D_];
__device__ float g_pre[BSROWS*D_];
__device__ float g_xa [BSROWS*D_];
__device__ float g_xb [BSROWS*D_];
__device__ float g_y  [BSROWS*D_];
__device__ float g_h  [BSROWS*DF_];
__device__ float g_gates[BSROWS*E_];
__device__ float g_gsum[E_];

// ---------------- tiny utility kernels ----------------
__global__ void zero_gsum_kernel() {
    if (threadIdx.x < E_) g_gsum[threadIdx.x] = 0.f;
}

__global__ void aux_kernel(float* out, int out_size) {
    float s = 0.f;
#pragma unroll
    for (int e = 0; e < E_; e++) {
        float mn = g_gsum[e] * (1.f / (float)BSROWS);
        s += mn * mn;
    }
    if (out_size > BSROWS * D_) out[BSROWS * D_] = (float)E_ * s;
}

// ---------------- helpers ----------------
__device__ __forceinline__ uint32_t f2tf32(float f) {
    uint32_t u;
    asm volatile("cvt.rna.tf32.f32 %0, %1;\n" : "=r"(u) : "f"(f));
    return u;
}

__device__ __forceinline__ void cp16(void* smem, const void* gmem) {
    uint32_t s = (uint32_t)__cvta_generic_to_shared(smem);
    asm volatile("cp.async.cg.shared.global [%0], [%1], 16;\n" :: "r"(s), "l"(gmem));
}
__device__ __forceinline__ void cp_commit() { asm volatile("cp.async.commit_group;\n"); }
__device__ __forceinline__ void cp_wait0()  { asm volatile("cp.async.wait_group 0;\n"); }

__device__ __forceinline__ void mma_tf32(float c[4], const uint32_t a[4], const uint32_t b[2]) {
    asm volatile(
        "mma.sync.aligned.m16n8k8.row.col.f32.tf32.tf32.f32 "
        "{%0,%1,%2,%3}, {%4,%5,%6,%7}, {%8,%9}, {%0,%1,%2,%3};\n"
        : "+f"(c[0]), "+f"(c[1]), "+f"(c[2]), "+f"(c[3])
        : "r"(a[0]), "r"(a[1]), "r"(a[2]), "r"(a[3]), "r"(b[0]), "r"(b[1]));
}

// ---------------- TF32 tensor-core GEMM with fused epilogue ----------------
#define FLAG_RELU  1
#define FLAG_ACCUM 2

// Block tile 128x128x16, 256 threads = 8 warps (2 x 4), warp tile 64x32.
__global__ void __launch_bounds__(256)
tgemm_kernel(const float* __restrict__ A, const float* __restrict__ W,
             const float* __restrict__ bias,
             const float* __restrict__ res,
             const float* __restrict__ rowscale, int rs_stride,
             float* __restrict__ C,
             int M, int N, int K, int flags)
{
    constexpr int BM = 128, BN = 128, BK = 16;
    constexpr int ASTR = 20;
    constexpr int BSTR = 136;
    __shared__ float As[2][BM][ASTR];
    __shared__ float Bs[2][BK][BSTR];

    const int tid  = threadIdx.x;
    const int warp = tid >> 5;
    const int lane = tid & 31;
    const int r = lane >> 2;
    const int c = lane & 3;
    const int wm = warp >> 2;
    const int wn = warp & 3;
    const int m0 = blockIdx.y * BM, n0 = blockIdx.x * BN;

    float acc[4][4][4];
#pragma unroll
    for (int i = 0; i < 4; i++)
#pragma unroll
        for (int j = 0; j < 4; j++)
#pragma unroll
            for (int q = 0; q < 4; q++) acc[i][j][q] = 0.f;

    const int a_row = tid >> 2;
    const int a_c4  = (tid & 3) * 4;
    const int b_row = tid >> 5;
    const int b_c4  = (tid & 31) * 4;

    const float* Ag = A + (size_t)(m0 + a_row) * K + a_c4;
    const float* Bg = W + (size_t)b_row * N + n0 + b_c4;

    const int ntiles = K / BK;

    {
        cp16(&As[0][a_row][a_c4],      Ag);
        cp16(&As[0][a_row + 64][a_c4], Ag + (size_t)64 * K);
        cp16(&Bs[0][b_row][b_c4],      Bg);
        cp16(&Bs[0][b_row + 8][b_c4],  Bg + (size_t)8 * N);
        cp_commit();
    }

    for (int t = 0; t < ntiles; t++) {
        cp_wait0();
        __syncthreads();
        const int cur = t & 1;
        if (t + 1 < ntiles) {
            const int nxt = cur ^ 1;
            const float* Agn = Ag + (size_t)(t + 1) * BK;
            const float* Bgn = Bg + (size_t)(t + 1) * BK * N;
            cp16(&As[nxt][a_row][a_c4],      Agn);
            cp16(&As[nxt][a_row + 64][a_c4], Agn + (size_t)64 * K);
            cp16(&Bs[nxt][b_row][b_c4],      Bgn);
            cp16(&Bs[nxt][b_row + 8][b_c4],  Bgn + (size_t)8 * N);
            cp_commit();
        }

#pragma unroll
        for (int ks = 0; ks < 2; ks++) {
            const int kk = ks * 8;
            uint32_t af[4][4];
            uint32_t bf[4][2];
#pragma unroll
            for (int mi = 0; mi < 4; mi++) {
                const int m = wm * 64 + mi * 16;
                af[mi][0] = f2tf32(As[cur][m + r][kk + c]);
                af[mi][1] = f2tf32(As[cur][m + r + 8][kk + c]);
                af[mi][2] = f2tf32(As[cur][m + r][kk + c + 4]);
                af[mi][3] = f2tf32(As[cur][m + r + 8][kk + c + 4]);
            }
#pragma unroll
            for (int nj = 0; nj < 4; nj++) {
                const int n = wn * 32 + nj * 8 + r;
                bf[nj][0] = f2tf32(Bs[cur][kk + c][n]);
                bf[nj][1] = f2tf32(Bs[cur][kk + c + 4][n]);
            }
#pragma unroll
            for (int mi = 0; mi < 4; mi++)
#pragma unroll
                for (int nj = 0; nj < 4; nj++)
                    mma_tf32(acc[mi][nj], af[mi], bf[nj]);
        }
    }

    const bool do_relu  = (flags & FLAG_RELU)  != 0;
    const bool do_accum = (flags & FLAG_ACCUM) != 0;
#pragma unroll
    for (int mi = 0; mi < 4; mi++) {
        const int mrow0 = m0 + wm * 64 + mi * 16 + r;
#pragma unroll
        for (int half = 0; half < 2; half++) {
            const int mrow = mrow0 + half * 8;
            const float rsv = rowscale ? rowscale[(size_t)mrow * rs_stride] : 1.f;
            const size_t rowbase = (size_t)mrow * N;
#pragma unroll
            for (int nj = 0; nj < 4; nj++) {
                const int ncol = n0 + wn * 32 + nj * 8 + 2 * c;
                float v0 = acc[mi][nj][half * 2 + 0];
                float v1 = acc[mi][nj][half * 2 + 1];
                if (bias) { v0 += bias[ncol]; v1 += bias[ncol + 1]; }
                if (do_relu) { v0 = fmaxf(v0, 0.f); v1 = fmaxf(v1, 0.f); }
                v0 *= rsv; v1 *= rsv;
                if (res) { v0 += res[rowbase + ncol]; v1 += res[rowbase + ncol + 1]; }
                if (do_accum) { v0 += C[rowbase + ncol]; v1 += C[rowbase + ncol + 1]; }
                *(float2*)&C[rowbase + ncol] = make_float2(v0, v1);
            }
        }
    }
}

static inline void gemm(const float* A, const float* W, const float* bias,
                        const float* res, const float* rs, int rss,
                        float* C, int M, int N, int K, int flags)
{
    dim3 grid(N / 128, M / 128);
    tgemm_kernel<<<grid, 256>>>(A, W, bias, res, rs, rss, C, M, N, K, flags);
}

// ---------------- tensor-core flash attention (tf32 mma, online softmax) ----
// 64 queries per CTA, one (b,h). 4 warps x 16 query rows. Key tiles of 64.
// Dynamic smem layout (floats):
//   Ks[64][68]  at KS_OFF   (K tile, converted in place to tf32 bits)
//   Vs[64][72]  at VS_OFF   (V tile, converted in place to tf32 bits)
//   Qs[64][68] / Ps[4][16][76]  union at PQ_OFF (Q fp32 staging, then P tf32)
#define KS_OFF 0
#define KS_STR 68
#define VS_OFF 4352
#define VS_STR 72
#define PQ_OFF 8960
#define QS_STR 68
#define PS_STR 76
#define PS_WARP 1216        // 16*76
#define ATTN_SMEM_FLOATS 13824
#define ATTN_SMEM_BYTES  55296

template<bool CAUSAL>
__global__ void __launch_bounds__(128)
fattn_kernel(const float* __restrict__ Q, const float* __restrict__ K,
             const float* __restrict__ V, float* __restrict__ O, int Sk)
{
    extern __shared__ float smf[];
    uint32_t* smu = (uint32_t*)smf;

    const int b = blockIdx.z, head = blockIdx.y, qt = blockIdx.x;
    const int tid  = threadIdx.x;
    const int w    = tid >> 5;
    const int lane = tid & 31;
    const int r = lane >> 2;     // 0..7
    const int c = lane & 3;      // 0..3
    const int wbase = w * 16;

    // ---- stage Q into smem (fp32), then build scaled tf32 A-fragments ----
    const float* Qg = Q + ((size_t)b * S_ + qt * 64) * D_ + head * DH_;
#pragma unroll
    for (int i = 0; i < 8; i++) {
        const int idx = i * 128 + tid;       // 1024 float4
        const int row = idx >> 4;
        const int c4  = (idx & 15) * 4;
        *(float4*)&smf[PQ_OFF + row * QS_STR + c4] =
            *(const float4*)(Qg + (size_t)row * D_ + c4);
    }
    __syncthreads();

    uint32_t aq[8][4];
#pragma unroll
    for (int kt = 0; kt < 8; kt++) {
        aq[kt][0] = f2tf32(0.125f * smf[PQ_OFF + (wbase + r)     * QS_STR + kt * 8 + c]);
        aq[kt][1] = f2tf32(0.125f * smf[PQ_OFF + (wbase + r + 8) * QS_STR + kt * 8 + c]);
        aq[kt][2] = f2tf32(0.125f * smf[PQ_OFF + (wbase + r)     * QS_STR + kt * 8 + c + 4]);
        aq[kt][3] = f2tf32(0.125f * smf[PQ_OFF + (wbase + r + 8) * QS_STR + kt * 8 + c + 4]);
    }

    float accO[8][4];
#pragma unroll
    for (int nj = 0; nj < 8; nj++)
#pragma unroll
        for (int q = 0; q < 4; q++) accO[nj][q] = 0.f;
    float mrow[2] = {-1e30f, -1e30f};
    float lrow[2] = {0.f, 0.f};

    const int ntiles = CAUSAL ? (qt + 1) : (Sk >> 6);

    for (int t = 0; t < ntiles; t++) {
        __syncthreads();   // all warps done reading Ks/Vs (and Qs on t=0)

        // ---- load K/V tile via cp.async ----
        const float* Kg = K + ((size_t)b * Sk + t * 64) * D_ + head * DH_;
        const float* Vg = V + ((size_t)b * Sk + t * 64) * D_ + head * DH_;
#pragma unroll
        for (int i = 0; i < 8; i++) {
            const int idx = i * 128 + tid;
            const int row = idx >> 4;
            const int c4  = (idx & 15) * 4;
            cp16(&smf[KS_OFF + row * KS_STR + c4], Kg + (size_t)row * D_ + c4);
            cp16(&smf[VS_OFF + row * VS_STR + c4], Vg + (size_t)row * D_ + c4);
        }
        cp_commit();
        cp_wait0();
        __syncthreads();

        // ---- in-place fp32 -> tf32 conversion of K/V tiles ----
#pragma unroll
        for (int i = 0; i < 18; i++) {
            const int v4 = i * 128 + tid;    // 2240 float4 in [0, 8960)
            if (v4 < 2240) {
                float4 f = *(float4*)&smf[v4 * 4];
                uint4 u = make_uint4(f2tf32(f.x), f2tf32(f.y), f2tf32(f.z), f2tf32(f.w));
                *(uint4*)&smu[v4 * 4] = u;
            }
        }
        __syncthreads();

        // ---- S = Q K^T (tf32 mma) ----
        float accS[8][4];
#pragma unroll
        for (int nj = 0; nj < 8; nj++)
#pragma unroll
            for (int q = 0; q < 4; q++) accS[nj][q] = 0.f;
#pragma unroll
        for (int kt = 0; kt < 8; kt++) {
#pragma unroll
            for (int nj = 0; nj < 8; nj++) {
                uint32_t bv[2];
                bv[0] = smu[KS_OFF + (nj * 8 + r) * KS_STR + kt * 8 + c];
                bv[1] = smu[KS_OFF + (nj * 8 + r) * KS_STR + kt * 8 + c + 4];
                mma_tf32(accS[nj], aq[kt], bv);
            }
        }

        // ---- causal mask (diagonal tile only) ----
        if (CAUSAL && t == qt) {
#pragma unroll
            for (int nj = 0; nj < 8; nj++) {
                const int key0 = nj * 8 + 2 * c;
#pragma unroll
                for (int q = 0; q < 4; q++) {
                    const int key  = key0 + (q & 1);
                    const int qrow = wbase + r + (q >> 1) * 8;
                    if (key > qrow) accS[nj][q] = -1e30f;
                }
            }
        }

        // ---- online softmax (per half: rows r and r+8) ----
#pragma unroll
        for (int hh = 0; hh < 2; hh++) {
            float vmax = -1e30f;
#pragma unroll
            for (int nj = 0; nj < 8; nj++)
                vmax = fmaxf(vmax, fmaxf(accS[nj][2 * hh], accS[nj][2 * hh + 1]));
            vmax = fmaxf(vmax, __shfl_xor_sync(0xffffffffu, vmax, 1));
            vmax = fmaxf(vmax, __shfl_xor_sync(0xffffffffu, vmax, 2));
            const float mnew = fmaxf(mrow[hh], vmax);
            const float corr = __expf(mrow[hh] - mnew);
            float psum = 0.f;
            uint32_t* Pw = smu + PQ_OFF + w * PS_WARP + (r + 8 * hh) * PS_STR + 2 * c;
#pragma unroll
            for (int nj = 0; nj < 8; nj++) {
                const float p0 = __expf(accS[nj][2 * hh]     - mnew);
                const float p1 = __expf(accS[nj][2 * hh + 1] - mnew);
                psum += p0 + p1;
                *(uint2*)&Pw[nj * 8] = make_uint2(f2tf32(p0), f2tf32(p1));
                accO[nj][2 * hh]     *= corr;
                accO[nj][2 * hh + 1] *= corr;
            }
            psum += __shfl_xor_sync(0xffffffffu, psum, 1);
            psum += __shfl_xor_sync(0xffffffffu, psum, 2);
            lrow[hh] = lrow[hh] * corr + psum;
            mrow[hh] = mnew;
        }
        __syncwarp();

        // ---- O += P V (tf32 mma) ----
        const uint32_t* Pb = smu + PQ_OFF + w * PS_WARP;
#pragma unroll
        for (int kt = 0; kt < 8; kt++) {
            uint32_t ap[4];
            ap[0] = Pb[r       * PS_STR + kt * 8 + c];
            ap[1] = Pb[(r + 8) * PS_STR + kt * 8 + c];
            ap[2] = Pb[r       * PS_STR + kt * 8 + c + 4];
            ap[3] = Pb[(r + 8) * PS_STR + kt * 8 + c + 4];
#pragma unroll
            for (int nj = 0; nj < 8; nj++) {
                uint32_t bv[2];
                bv[0] = smu[VS_OFF + (kt * 8 + c)     * VS_STR + nj * 8 + r];
                bv[1] = smu[VS_OFF + (kt * 8 + c + 4) * VS_STR + nj * 8 + r];
                mma_tf32(accO[nj], ap, bv);
            }
        }
    }

    // ---- normalize and write ----
    const float inv0 = 1.f / lrow[0];
    const float inv1 = 1.f / lrow[1];
    const int row0 = qt * 64 + wbase + r;
    float* Ob = O + ((size_t)b * S_ + row0) * D_ + head * DH_;
#pragma unroll
    for (int nj = 0; nj < 8; nj++) {
        const int col = nj * 8 + 2 * c;
        *(float2*)&Ob[col] = make_float2(accO[nj][0] * inv0, accO[nj][1] * inv0);
        *(float2*)&Ob[(size_t)8 * D_ + col] = make_float2(accO[nj][2] * inv1, accO[nj][3] * inv1);
    }
}

// ---------------- LayerNorm: out = LN(a + b?) * g + beta ----------------
__global__ void __launch_bounds__(256)
ln_kernel(const float* __restrict__ a, const float* __restrict__ b,
          const float* __restrict__ g, const float* __restrict__ be,
          float* __restrict__ out)
{
    const int row = blockIdx.x;
    const int t = threadIdx.x;
    const size_t base = (size_t)row * D_;
    float v0 = a[base + t];
    float v1 = a[base + t + 256];
    if (b) { v0 += b[base + t]; v1 += b[base + t + 256]; }

    float s = v0 + v1, ss = v0 * v0 + v1 * v1;
    const int lane = t & 31, w = t >> 5;
    __shared__ float shs[8], shss[8];
#pragma unroll
    for (int off = 16; off; off >>= 1) {
        s  += __shfl_down_sync(0xffffffffu, s,  off);
        ss += __shfl_down_sync(0xffffffffu, ss, off);
    }
    if (lane == 0) { shs[w] = s; shss[w] = ss; }
    __syncthreads();
    __shared__ float mean_sh, inv_sh;
    if (t == 0) {
        float S = 0.f, SS = 0.f;
#pragma unroll
        for (int i = 0; i < 8; i++) { S += shs[i]; SS += shss[i]; }
        float mean = S * (1.f / (float)D_);
        float var  = SS * (1.f / (float)D_) - mean * mean;
        mean_sh = mean;
        inv_sh  = rsqrtf(var + EPS_);
    }
    __syncthreads();
    float mean = mean_sh, inv = inv_sh;
    out[base + t]       = (v0 - mean) * inv * g[t]       + be[t];
    out[base + t + 256] = (v1 - mean) * inv * g[t + 256] + be[t + 256];
}

// ---------------- gate: softmax(x @ gw + gb) + per-expert sums ----------------
__global__ void __launch_bounds__(256)
gate_kernel(const float* __restrict__ x, const float* __restrict__ gw,
            const float* __restrict__ gb)
{
    const int warp = (blockIdx.x * blockDim.x + threadIdx.x) >> 5;
    const int lane = threadIdx.x & 31;
    if (warp >= BSROWS) return;
    const float* xr = x + (size_t)warp * D_;
    float a0 = 0.f, a1 = 0.f, a2 = 0.f, a3 = 0.f;
    for (int d = lane; d < D_; d += 32) {
        float xv = xr[d];
        const float* wr = gw + (size_t)d * E_;
        a0 += xv * wr[0]; a1 += xv * wr[1]; a2 += xv * wr[2]; a3 += xv * wr[3];
    }
#pragma unroll
    for (int off = 16; off; off >>= 1) {
        a0 += __shfl_down_sync(0xffffffffu, a0, off);
        a1 += __shfl_down_sync(0xffffffffu, a1, off);
        a2 += __shfl_down_sync(0xffffffffu, a2, off);
        a3 += __shfl_down_sync(0xffffffffu, a3, off);
    }
    if (lane == 0) {
        float l0 = a0 + gb[0], l1 = a1 + gb[1], l2 = a2 + gb[2], l3 = a3 + gb[3];
        float mx = fmaxf(fmaxf(l0, l1), fmaxf(l2, l3));
        float e0 = __expf(l0 - mx), e1 = __expf(l1 - mx);
        float e2 = __expf(l2 - mx), e3 = __expf(l3 - mx);
        float si = 1.f / (e0 + e1 + e2 + e3);
        float p0 = e0 * si, p1 = e1 * si, p2 = e2 * si, p3 = e3 * si;
        float* gp = g_gates + (size_t)warp * E_;
        gp[0] = p0; gp[1] = p1; gp[2] = p2; gp[3] = p3;
        atomicAdd(&g_gsum[0], p0);
        atomicAdd(&g_gsum[1], p1);
        atomicAdd(&g_gsum[2], p2);
        atomicAdd(&g_gsum[3], p3);
    }
}

// ---------------- host orchestration ----------------
extern "C" void kernel_launch(void* const* d_in, const int* in_sizes, int n_in,
                              void* d_out, int out_size)
{
    const float* x      = (const float*)d_in[0];
    const float* cross  = (const float*)d_in[1];
    const float* sa_wq  = (const float*)d_in[2];
    const float* sa_bq  = (const float*)d_in[3];
    const float* sa_wk  = (const float*)d_in[4];
    const float* sa_bk  = (const float*)d_in[5];
    const float* sa_wv  = (const float*)d_in[6];
    const float* sa_bv  = (const float*)d_in[7];
    const float* sa_wo  = (const float*)d_in[8];
    const float* sa_bo  = (const float*)d_in[9];
    const float* ca_wq  = (const float*)d_in[10];
    const float* ca_bq  = (const float*)d_in[11];
    const float* ca_wk  = (const float*)d_in[12];
    const float* ca_bk  = (const float*)d_in[13];
    const float* ca_wv  = (const float*)d_in[14];
    const float* ca_bv  = (const float*)d_in[15];
    const float* ca_wo  = (const float*)d_in[16];
    const float* ca_bo  = (const float*)d_in[17];
    const float* gate_w = (const float*)d_in[18];
    const float* gate_b = (const float*)d_in[19];
    const float* exp_w1 = (const float*)d_in[20];
    const float* exp_b1 = (const float*)d_in[21];
    const float* exp_w2 = (const float*)d_in[22];
    const float* exp_b2 = (const float*)d_in[23];
    const float* n1_g   = (const float*)d_in[24];
    const float* n1_b   = (const float*)d_in[25];
    const float* n2_g   = (const float*)d_in[26];
    const float* n2_b   = (const float*)d_in[27];
    const float* n3_g   = (const float*)d_in[28];
    const float* n3_b   = (const float*)d_in[29];
    float* out = (float*)d_out;

    float *q, *k, *v, *att, *pre, *xa, *xb, *y, *h, *gates;
    cudaGetSymbolAddress((void**)&q,    g_q);
    cudaGetSymbolAddress((void**)&k,    g_k);
    cudaGetSymbolAddress((void**)&v,    g_v);
    cudaGetSymbolAddress((void**)&att,  g_att);
    cudaGetSymbolAddress((void**)&pre,  g_pre);
    cudaGetSymbolAddress((void**)&xa,   g_xa);
    cudaGetSymbolAddress((void**)&xb,   g_xb);
    cudaGetSymbolAddress((void**)&y,    g_y);
    cudaGetSymbolAddress((void**)&h,    g_h);
    cudaGetSymbolAddress((void**)&gates, g_gates);

    static bool attr_done = false;
    if (!attr_done) {
        cudaFuncSetAttribute(fattn_kernel<true>,
                             cudaFuncAttributeMaxDynamicSharedMemorySize, ATTN_SMEM_BYTES);
        cudaFuncSetAttribute(fattn_kernel<false>,
                             cudaFuncAttributeMaxDynamicSharedMemorySize, ATTN_SMEM_BYTES);
        attr_done = true;
    }

    zero_gsum_kernel<<<1, 32>>>();

    // ---- self-attention block ----
    gemm(x, sa_wq, sa_bq, nullptr, nullptr, 0, q, BSROWS, D_, D_, 0);
    gemm(x, sa_wk, sa_bk, nullptr, nullptr, 0, k, BSROWS, D_, D_, 0);
    gemm(x, sa_wv, sa_bv, nullptr, nullptr, 0, v, BSROWS, D_, D_, 0);
    fattn_kernel<true><<<dim3(S_ / 64, H_, B_), 128, ATTN_SMEM_BYTES>>>(q, k, v, att, S_);
    gemm(att, sa_wo, sa_bo, /*res=*/x, nullptr, 0, pre, BSROWS, D_, D_, 0);
    ln_kernel<<<BSROWS, 256>>>(pre, nullptr, n1_g, n1_b, xa);

    // ---- cross-attention block ----
    gemm(xa,    ca_wq, ca_bq, nullptr, nullptr, 0, q, BSROWS, D_, D_, 0);
    gemm(cross, ca_wk, ca_bk, nullptr, nullptr, 0, k, BTROWS, D_, D_, 0);
    gemm(cross, ca_wv, ca_bv, nullptr, nullptr, 0, v, BTROWS, D_, D_, 0);
    fattn_kernel<false><<<dim3(S_ / 64, H_, B_), 128, ATTN_SMEM_BYTES>>>(q, k, v, att, T_);
    gemm(att, ca_wo, ca_bo, /*res=*/xa, nullptr, 0, pre, BSROWS, D_, D_, 0);
    ln_kernel<<<BSROWS, 256>>>(pre, nullptr, n2_g, n2_b, xb);

    // ---- MoE ----
    gate_kernel<<<(BSROWS * 32 + 255) / 256, 256>>>(xb, gate_w, gate_b);
    aux_kernel<<<1, 1>>>(out, out_size);
    for (int e = 0; e < E_; e++) {
        gemm(xb, exp_w1 + (size_t)e * D_ * DF_, exp_b1 + (size_t)e * DF_,
             nullptr, nullptr, 0, h, BSROWS, DF_, D_, FLAG_RELU);
        gemm(h, exp_w2 + (size_t)e * DF_ * D_, exp_b2 + (size_t)e * D_,
             nullptr, gates + e, E_, y, BSROWS, D_, DF_, e ? FLAG_ACCUM : 0);
    }
    ln_kernel<<<BSROWS, 256>>>(xb, y, n3_g, n3_b, out);
}

// round 4
// speedup vs baseline: 4.7820x; 1.4268x over previous
#include <cuda_runtime.h>
#include <cuda_bf16.h>
#include <cstdint>

// Problem constants
#define B_  16
#define S_  1024
#define T_  512
#define D_  512
#define H_  8
#define DH_ 64
#define DF_ 2048
#define E_  4
#define BSROWS (B_*S_)    // 16384
#define BTROWS (B_*T_)    // 8192
#define EPS_ 1e-5f

// ---------------- scratch (static __device__ — no allocation) ----------------
__device__ float          g_qkv  [BSROWS*1536];   // self QKV fp32; reused: cross q (0) + cross kv (at BSROWS*512)
__device__ __nv_bfloat16  g_attbf[BSROWS*D_];
__device__ float          g_pre  [BSROWS*D_];
__device__ float          g_xa   [BSROWS*D_];
__device__ __nv_bfloat16  g_xabf [BSROWS*D_];
__device__ float          g_xb   [BSROWS*D_];
__device__ __nv_bfloat16  g_xbbf [BSROWS*D_];
__device__ float          g_y    [BSROWS*D_];
__device__ __nv_bfloat16  g_hbf  [(size_t)BSROWS*E_*DF_];   // 16384 x 8192
__device__ __nv_bfloat16  g_xbf  [BSROWS*D_];
__device__ __nv_bfloat16  g_crbf [BTROWS*D_];
__device__ float          g_gates[BSROWS*E_];
__device__ float          g_gsum [E_];
// packed / transposed weights (bf16, [N][K] k-contiguous)
__device__ __nv_bfloat16  g_wqkvt [1536*D_];
__device__ float          g_bqkv  [1536];
__device__ __nv_bfloat16  g_wsaot [D_*D_];
__device__ __nv_bfloat16  g_wcaqt [D_*D_];
__device__ __nv_bfloat16  g_wcakvt[1024*D_];
__device__ float          g_bcakv [1024];
__device__ __nv_bfloat16  g_wcaot [D_*D_];
__device__ __nv_bfloat16  g_w1t   [(size_t)E_*DF_*D_];      // [8192][512]
__device__ float          g_b1p   [E_*DF_];
__device__ __nv_bfloat16  g_w2t   [(size_t)D_*E_*DF_];      // [512][8192]

// ---------------- tiny utility kernels ----------------
__global__ void zero_gsum_kernel() {
    if (threadIdx.x < E_) g_gsum[threadIdx.x] = 0.f;
}

__global__ void aux_kernel(float* out, int out_size) {
    float s = 0.f;
#pragma unroll
    for (int e = 0; e < E_; e++) {
        float mn = g_gsum[e] * (1.f / (float)BSROWS);
        s += mn * mn;
    }
    if (out_size > BSROWS * D_) out[BSROWS * D_] = (float)E_ * s;
}

__global__ void copyf_kernel(const float* __restrict__ s, float* __restrict__ d, int n) {
    int i = blockIdx.x * blockDim.x + threadIdx.x;
    if (i < n) d[i] = s[i];
}

// fp32 -> bf16 elementwise (n divisible by 4)
__global__ void cvtbf_kernel(const float* __restrict__ s, __nv_bfloat16* __restrict__ d, int n4) {
    int i = blockIdx.x * blockDim.x + threadIdx.x;
    if (i < n4) {
        float4 f = ((const float4*)s)[i];
        __nv_bfloat162* dd = (__nv_bfloat162*)d + i * 2;
        dd[0] = __floats2bfloat162_rn(f.x, f.y);
        dd[1] = __floats2bfloat162_rn(f.z, f.w);
    }
}

// transpose-pack: dst[(dRow0 + c)*dstLd + dCol0 + r] = bf16(src[r*srcCols + c])
// grid: (srcCols/32, srcRows/32), block (32,8). Dims multiples of 32.
__global__ void tpack_kernel(const float* __restrict__ src, int srcCols,
                             __nv_bfloat16* __restrict__ dst, int dstLd,
                             int dRow0, int dCol0)
{
    __shared__ float t[32][33];
    const int c0 = blockIdx.x * 32, r0 = blockIdx.y * 32;
#pragma unroll
    for (int i = 0; i < 4; i++) {
        int rr = threadIdx.y + i * 8;
        t[rr][threadIdx.x] = src[(size_t)(r0 + rr) * srcCols + c0 + threadIdx.x];
    }
    __syncthreads();
#pragma unroll
    for (int i = 0; i < 4; i++) {
        int rr = threadIdx.y + i * 8;
        dst[(size_t)(dRow0 + c0 + rr) * dstLd + dCol0 + r0 + threadIdx.x] =
            __float2bfloat16_rn(t[threadIdx.x][rr]);
    }
}

// ---------------- helpers ----------------
__device__ __forceinline__ uint32_t f2tf32(float f) {
    uint32_t u;
    asm volatile("cvt.rna.tf32.f32 %0, %1;\n" : "=r"(u) : "f"(f));
    return u;
}

__device__ __forceinline__ void cp16(void* smem, const void* gmem) {
    uint32_t s = (uint32_t)__cvta_generic_to_shared(smem);
    asm volatile("cp.async.cg.shared.global [%0], [%1], 16;\n" :: "r"(s), "l"(gmem));
}
__device__ __forceinline__ void cp_commit() { asm volatile("cp.async.commit_group;\n"); }
__device__ __forceinline__ void cp_wait0()  { asm volatile("cp.async.wait_group 0;\n"); }
__device__ __forceinline__ void cp_wait1()  { asm volatile("cp.async.wait_group 1;\n"); }

__device__ __forceinline__ void mma_tf32(float c[4], const uint32_t a[4], const uint32_t b[2]) {
    asm volatile(
        "mma.sync.aligned.m16n8k8.row.col.f32.tf32.tf32.f32 "
        "{%0,%1,%2,%3}, {%4,%5,%6,%7}, {%8,%9}, {%0,%1,%2,%3};\n"
        : "+f"(c[0]), "+f"(c[1]), "+f"(c[2]), "+f"(c[3])
        : "r"(a[0]), "r"(a[1]), "r"(a[2]), "r"(a[3]), "r"(b[0]), "r"(b[1]));
}

__device__ __forceinline__ void mma_bf16(float c[4], const uint32_t a[4], const uint32_t b[2]) {
    asm volatile(
        "mma.sync.aligned.m16n8k16.row.col.f32.bf16.bf16.f32 "
        "{%0,%1,%2,%3}, {%4,%5,%6,%7}, {%8,%9}, {%0,%1,%2,%3};\n"
        : "+f"(c[0]), "+f"(c[1]), "+f"(c[2]), "+f"(c[3])
        : "r"(a[0]), "r"(a[1]), "r"(a[2]), "r"(a[3]), "r"(b[0]), "r"(b[1]));
}

// ---------------- BF16 tensor-core GEMM, fused epilogue ----------------
// C[M,N] = epi(A[M,K](bf16,lda) @ Wt[N,K](bf16)^T + bias)
// flags: 1 relu, 2 expert gate scale (N=8192: e = n0>>11), 4 write fp32 C, 8 write bf16 Cb
#define FLAG_RELU  1
#define FLAG_GATE  2
#define FLAG_WF32  4
#define FLAG_WBF16 8

// 128x128x32 tiles, 3-stage cp.async, 8 warps (2x4), warp tile 64x32.
// smem: per stage A[128][40] + B[128][40] bf16 (padded stride 40 -> conflict-free).
#define BG_STAGE_ELEMS 5120           // 128*40 bf16
#define BG_SMEM_BYTES  61440          // 3 * 2 * 5120 * 2

__global__ void __launch_bounds__(256)
bgemm_kernel(const __nv_bfloat16* __restrict__ A, int lda,
             const __nv_bfloat16* __restrict__ W, int K,
             const float* __restrict__ bias,
             const float* __restrict__ res,
             const float* __restrict__ gates,
             float* __restrict__ Cf, __nv_bfloat16* __restrict__ Cb,
             int ldc, int N, int flags)
{
    extern __shared__ __nv_bfloat16 smb[];

    const int tid  = threadIdx.x;
    const int warp = tid >> 5;
    const int lane = tid & 31;
    const int r = lane >> 2;     // 0..7
    const int c = lane & 3;      // 0..3
    const int wm = warp >> 2;    // 0..1
    const int wn = warp & 3;     // 0..3
    const int m0 = blockIdx.y * 128, n0 = blockIdx.x * 128;

    const int lrow = tid >> 1;   // 0..127
    const int lch  = tid & 1;    // chunk 0/1 (plus +2)

    float acc[4][4][4];
#pragma unroll
    for (int i = 0; i < 4; i++)
#pragma unroll
        for (int j = 0; j < 4; j++)
#pragma unroll
            for (int q = 0; q < 4; q++) acc[i][j][q] = 0.f;

    const int ntk = K >> 5;

    const __nv_bfloat16* Abase = A + (size_t)(m0 + lrow) * lda;
    const __nv_bfloat16* Bbase = W + (size_t)(n0 + lrow) * K;

#define LOAD_STAGE(s, t) do {                                                   \
        const int k0_ = (t) * 32;                                               \
        __nv_bfloat16* As_ = smb + (s) * BG_STAGE_ELEMS + lrow * 40;            \
        __nv_bfloat16* Bs_ = smb + (3 + (s)) * BG_STAGE_ELEMS + lrow * 40;      \
        cp16(As_ + lch * 8,       Abase + k0_ + lch * 8);                       \
        cp16(As_ + (lch + 2) * 8, Abase + k0_ + (lch + 2) * 8);                 \
        cp16(Bs_ + lch * 8,       Bbase + k0_ + lch * 8);                       \
        cp16(Bs_ + (lch + 2) * 8, Bbase + k0_ + (lch + 2) * 8);                 \
    } while (0)

    LOAD_STAGE(0, 0); cp_commit();
    LOAD_STAGE(1, 1); cp_commit();

    for (int t = 0; t < ntk; t++) {
        cp_wait1();
        __syncthreads();
        if (t + 2 < ntk) { LOAD_STAGE((t + 2) % 3, t + 2); }
        cp_commit();

        const int s = t % 3;
        const uint32_t* Au = (const uint32_t*)(smb + s * BG_STAGE_ELEMS);
        const uint32_t* Bu = (const uint32_t*)(smb + (3 + s) * BG_STAGE_ELEMS);
#pragma unroll
        for (int ks = 0; ks < 2; ks++) {
            const int h = ks * 8;    // uint32 offset within row (k/2)
            uint32_t af[4][4];
            uint32_t bf4[4][2];
#pragma unroll
            for (int mi = 0; mi < 4; mi++) {
                const int row = wm * 64 + mi * 16 + r;
                af[mi][0] = Au[row * 20 + h + c];
                af[mi][1] = Au[(row + 8) * 20 + h + c];
                af[mi][2] = Au[row * 20 + h + c + 4];
                af[mi][3] = Au[(row + 8) * 20 + h + c + 4];
            }
#pragma unroll
            for (int nj = 0; nj < 4; nj++) {
                const int n = wn * 32 + nj * 8 + r;
                bf4[nj][0] = Bu[n * 20 + h + c];
                bf4[nj][1] = Bu[n * 20 + h + c + 4];
            }
#pragma unroll
            for (int mi = 0; mi < 4; mi++)
#pragma unroll
                for (int nj = 0; nj < 4; nj++)
                    mma_bf16(acc[mi][nj], af[mi], bf4[nj]);
        }
    }

    // ---------------- epilogue ----------------
    const bool do_relu = (flags & FLAG_RELU) != 0;
    const bool do_gate = (flags & FLAG_GATE) != 0;
    const bool wf32    = (flags & FLAG_WF32) != 0;
    const bool wbf16   = (flags & FLAG_WBF16) != 0;
    const int  eblk    = n0 >> 11;   // expert id for gate scaling (2048 cols/expert)

#pragma unroll
    for (int mi = 0; mi < 4; mi++) {
#pragma unroll
        for (int half = 0; half < 2; half++) {
            const int mrow = m0 + wm * 64 + mi * 16 + r + half * 8;
            const float rsv = do_gate ? gates[(size_t)mrow * E_ + eblk] : 1.f;
            const size_t rowbase = (size_t)mrow * ldc;
#pragma unroll
            for (int nj = 0; nj < 4; nj++) {
                const int ncol = n0 + wn * 32 + nj * 8 + 2 * c;
                float v0 = acc[mi][nj][half * 2 + 0];
                float v1 = acc[mi][nj][half * 2 + 1];
                if (bias) { v0 += bias[ncol]; v1 += bias[ncol + 1]; }
                if (do_relu) { v0 = fmaxf(v0, 0.f); v1 = fmaxf(v1, 0.f); }
                v0 *= rsv; v1 *= rsv;
                if (res) { v0 += res[rowbase + ncol]; v1 += res[rowbase + ncol + 1]; }
                if (wf32)  *(float2*)&Cf[rowbase + ncol] = make_float2(v0, v1);
                if (wbf16) *(__nv_bfloat162*)&Cb[rowbase + ncol] = __floats2bfloat162_rn(v0, v1);
            }
        }
    }
#undef LOAD_STAGE
}

static inline void bgemm(const __nv_bfloat16* A, int lda, const __nv_bfloat16* W, int K,
                         const float* bias, const float* res, const float* gates,
                         float* Cf, __nv_bfloat16* Cb, int ldc, int M, int N, int flags)
{
    dim3 grid(N / 128, M / 128);
    bgemm_kernel<<<grid, 256, BG_SMEM_BYTES>>>(A, lda, W, K, bias, res, gates, Cf, Cb, ldc, N, flags);
}

// ---------------- tensor-core flash attention (tf32 mma, online softmax) ----
// 64 queries per CTA, one (b,h). 4 warps x 16 query rows. Key tiles of 64.
// Reads fp32 Q/K/V with row strides q_ld / kv_ld; writes bf16 O ([.,512], head-packed).
#define KS_OFF 0
#define KS_STR 68
#define VS_OFF 4352
#define VS_STR 72
#define PQ_OFF 8960
#define QS_STR 68
#define PS_STR 76
#define PS_WARP 1216        // 16*76
#define ATTN_SMEM_BYTES  55296

template<bool CAUSAL>
__global__ void __launch_bounds__(128)
fattn_kernel(const float* __restrict__ Q, int q_ld,
             const float* __restrict__ Kp, const float* __restrict__ Vp, int kv_ld,
             __nv_bfloat16* __restrict__ Ob, int Sk)
{
    extern __shared__ float smf[];
    uint32_t* smu = (uint32_t*)smf;

    const int b = blockIdx.z, head = blockIdx.y, qt = blockIdx.x;
    const int tid  = threadIdx.x;
    const int w    = tid >> 5;
    const int lane = tid & 31;
    const int r = lane >> 2;     // 0..7
    const int c = lane & 3;      // 0..3
    const int wbase = w * 16;

    // ---- stage Q into smem (fp32), then build scaled tf32 A-fragments ----
    const float* Qg = Q + ((size_t)b * S_ + qt * 64) * q_ld + head * DH_;
#pragma unroll
    for (int i = 0; i < 8; i++) {
        const int idx = i * 128 + tid;       // 1024 float4
        const int row = idx >> 4;
        const int c4  = (idx & 15) * 4;
        *(float4*)&smf[PQ_OFF + row * QS_STR + c4] =
            *(const float4*)(Qg + (size_t)row * q_ld + c4);
    }
    __syncthreads();

    uint32_t aq[8][4];
#pragma unroll
    for (int kt = 0; kt < 8; kt++) {
        aq[kt][0] = f2tf32(0.125f * smf[PQ_OFF + (wbase + r)     * QS_STR + kt * 8 + c]);
        aq[kt][1] = f2tf32(0.125f * smf[PQ_OFF + (wbase + r + 8) * QS_STR + kt * 8 + c]);
        aq[kt][2] = f2tf32(0.125f * smf[PQ_OFF + (wbase + r)     * QS_STR + kt * 8 + c + 4]);
        aq[kt][3] = f2tf32(0.125f * smf[PQ_OFF + (wbase + r + 8) * QS_STR + kt * 8 + c + 4]);
    }

    float accO[8][4];
#pragma unroll
    for (int nj = 0; nj < 8; nj++)
#pragma unroll
        for (int q = 0; q < 4; q++) accO[nj][q] = 0.f;
    float mrow[2] = {-1e30f, -1e30f};
    float lrow[2] = {0.f, 0.f};

    const int ntiles = CAUSAL ? (qt + 1) : (Sk >> 6);

    for (int t = 0; t < ntiles; t++) {
        __syncthreads();

        const float* Kg = Kp + ((size_t)b * Sk + t * 64) * kv_ld + head * DH_;
        const float* Vg = Vp + ((size_t)b * Sk + t * 64) * kv_ld + head * DH_;
#pragma unroll
        for (int i = 0; i < 8; i++) {
            const int idx = i * 128 + tid;
            const int row = idx >> 4;
            const int c4  = (idx & 15) * 4;
            cp16(&smf[KS_OFF + row * KS_STR + c4], Kg + (size_t)row * kv_ld + c4);
            cp16(&smf[VS_OFF + row * VS_STR + c4], Vg + (size_t)row * kv_ld + c4);
        }
        cp_commit();
        cp_wait0();
        __syncthreads();

        // in-place fp32 -> tf32 conversion of K/V tiles
#pragma unroll
        for (int i = 0; i < 18; i++) {
            const int v4 = i * 128 + tid;
            if (v4 < 2240) {
                float4 f = *(float4*)&smf[v4 * 4];
                uint4 u = make_uint4(f2tf32(f.x), f2tf32(f.y), f2tf32(f.z), f2tf32(f.w));
                *(uint4*)&smu[v4 * 4] = u;
            }
        }
        __syncthreads();

        // ---- S = Q K^T ----
        float accS[8][4];
#pragma unroll
        for (int nj = 0; nj < 8; nj++)
#pragma unroll
            for (int q = 0; q < 4; q++) accS[nj][q] = 0.f;
#pragma unroll
        for (int kt = 0; kt < 8; kt++) {
#pragma unroll
            for (int nj = 0; nj < 8; nj++) {
                uint32_t bv[2];
                bv[0] = smu[KS_OFF + (nj * 8 + r) * KS_STR + kt * 8 + c];
                bv[1] = smu[KS_OFF + (nj * 8 + r) * KS_STR + kt * 8 + c + 4];
                mma_tf32(accS[nj], aq[kt], bv);
            }
        }

        if (CAUSAL && t == qt) {
#pragma unroll
            for (int nj = 0; nj < 8; nj++) {
                const int key0 = nj * 8 + 2 * c;
#pragma unroll
                for (int q = 0; q < 4; q++) {
                    const int key  = key0 + (q & 1);
                    const int qrow = wbase + r + (q >> 1) * 8;
                    if (key > qrow) accS[nj][q] = -1e30f;
                }
            }
        }

        // ---- online softmax ----
#pragma unroll
        for (int hh = 0; hh < 2; hh++) {
            float vmax = -1e30f;
#pragma unroll
            for (int nj = 0; nj < 8; nj++)
                vmax = fmaxf(vmax, fmaxf(accS[nj][2 * hh], accS[nj][2 * hh + 1]));
            vmax = fmaxf(vmax, __shfl_xor_sync(0xffffffffu, vmax, 1));
            vmax = fmaxf(vmax, __shfl_xor_sync(0xffffffffu, vmax, 2));
            const float mnew = fmaxf(mrow[hh], vmax);
            const float corr = __expf(mrow[hh] - mnew);
            float psum = 0.f;
            uint32_t* Pw = smu + PQ_OFF + w * PS_WARP + (r + 8 * hh) * PS_STR + 2 * c;
#pragma unroll
            for (int nj = 0; nj < 8; nj++) {
                const float p0 = __expf(accS[nj][2 * hh]     - mnew);
                const float p1 = __expf(accS[nj][2 * hh + 1] - mnew);
                psum += p0 + p1;
                *(uint2*)&Pw[nj * 8] = make_uint2(f2tf32(p0), f2tf32(p1));
                accO[nj][2 * hh]     *= corr;
                accO[nj][2 * hh + 1] *= corr;
            }
            psum += __shfl_xor_sync(0xffffffffu, psum, 1);
            psum += __shfl_xor_sync(0xffffffffu, psum, 2);
            lrow[hh] = lrow[hh] * corr + psum;
            mrow[hh] = mnew;
        }
        __syncwarp();

        // ---- O += P V ----
        const uint32_t* Pb = smu + PQ_OFF + w * PS_WARP;
#pragma unroll
        for (int kt = 0; kt < 8; kt++) {
            uint32_t ap[4];
            ap[0] = Pb[r       * PS_STR + kt * 8 + c];
            ap[1] = Pb[(r + 8) * PS_STR + kt * 8 + c];
            ap[2] = Pb[r       * PS_STR + kt * 8 + c + 4];
            ap[3] = Pb[(r + 8) * PS_STR + kt * 8 + c + 4];
#pragma unroll
            for (int nj = 0; nj < 8; nj++) {
                uint32_t bv[2];
                bv[0] = smu[VS_OFF + (kt * 8 + c)     * VS_STR + nj * 8 + r];
                bv[1] = smu[VS_OFF + (kt * 8 + c + 4) * VS_STR + nj * 8 + r];
                mma_tf32(accO[nj], ap, bv);
            }
        }
    }

    // ---- normalize and write bf16 ----
    const float inv0 = 1.f / lrow[0];
    const float inv1 = 1.f / lrow[1];
    const int row0 = qt * 64 + wbase + r;
    __nv_bfloat16* Obp = Ob + ((size_t)b * S_ + row0) * D_ + head * DH_;
#pragma unroll
    for (int nj = 0; nj < 8; nj++) {
        const int col = nj * 8 + 2 * c;
        *(__nv_bfloat162*)&Obp[col] = __floats2bfloat162_rn(accO[nj][0] * inv0, accO[nj][1] * inv0);
        *(__nv_bfloat162*)&Obp[(size_t)8 * D_ + col] =
            __floats2bfloat162_rn(accO[nj][2] * inv1, accO[nj][3] * inv1);
    }
}

// ---------------- LayerNorm: out = LN(a) * g + beta, dual fp32/bf16 out ------
__global__ void __launch_bounds__(256)
ln_kernel(const float* __restrict__ a,
          const float* __restrict__ g, const float* __restrict__ be,
          float* __restrict__ out, __nv_bfloat16* __restrict__ outb)
{
    const int row = blockIdx.x;
    const int t = threadIdx.x;
    const size_t base = (size_t)row * D_;
    float v0 = a[base + t];
    float v1 = a[base + t + 256];

    float s = v0 + v1, ss = v0 * v0 + v1 * v1;
    const int lane = t & 31, w = t >> 5;
    __shared__ float shs[8], shss[8];
#pragma unroll
    for (int off = 16; off; off >>= 1) {
        s  += __shfl_down_sync(0xffffffffu, s,  off);
        ss += __shfl_down_sync(0xffffffffu, ss, off);
    }
    if (lane == 0) { shs[w] = s; shss[w] = ss; }
    __syncthreads();
    __shared__ float mean_sh, inv_sh;
    if (t == 0) {
        float S = 0.f, SS = 0.f;
#pragma unroll
        for (int i = 0; i < 8; i++) { S += shs[i]; SS += shss[i]; }
        float mean = S * (1.f / (float)D_);
        float var  = SS * (1.f / (float)D_) - mean * mean;
        mean_sh = mean;
        inv_sh  = rsqrtf(var + EPS_);
    }
    __syncthreads();
    float mean = mean_sh, inv = inv_sh;
    float o0 = (v0 - mean) * inv * g[t]       + be[t];
    float o1 = (v1 - mean) * inv * g[t + 256] + be[t + 256];
    out[base + t]       = o0;
    out[base + t + 256] = o1;
    if (outb) {
        outb[base + t]       = __float2bfloat16_rn(o0);
        outb[base + t + 256] = __float2bfloat16_rn(o1);
    }
}

// ---------------- LN3: out = LN(xb + y + sum_e gate_e*b2_e) * g + beta -------
__global__ void __launch_bounds__(256)
ln3_kernel(const float* __restrict__ xb, const float* __restrict__ y,
           const float* __restrict__ gates, const float* __restrict__ b2,
           const float* __restrict__ g, const float* __restrict__ be,
           float* __restrict__ out)
{
    const int row = blockIdx.x;
    const int t = threadIdx.x;
    const size_t base = (size_t)row * D_;
    const float ga0 = gates[(size_t)row * E_ + 0];
    const float ga1 = gates[(size_t)row * E_ + 1];
    const float ga2 = gates[(size_t)row * E_ + 2];
    const float ga3 = gates[(size_t)row * E_ + 3];
    float gb0 = ga0 * b2[t]        + ga1 * b2[D_ + t]        + ga2 * b2[2*D_ + t]        + ga3 * b2[3*D_ + t];
    float gb1 = ga0 * b2[t + 256]  + ga1 * b2[D_ + t + 256]  + ga2 * b2[2*D_ + t + 256]  + ga3 * b2[3*D_ + t + 256];
    float v0 = xb[base + t]       + y[base + t]       + gb0;
    float v1 = xb[base + t + 256] + y[base + t + 256] + gb1;

    float s = v0 + v1, ss = v0 * v0 + v1 * v1;
    const int lane = t & 31, w = t >> 5;
    __shared__ float shs[8], shss[8];
#pragma unroll
    for (int off = 16; off; off >>= 1) {
        s  += __shfl_down_sync(0xffffffffu, s,  off);
        ss += __shfl_down_sync(0xffffffffu, ss, off);
    }
    if (lane == 0) { shs[w] = s; shss[w] = ss; }
    __syncthreads();
    __shared__ float mean_sh, inv_sh;
    if (t == 0) {
        float S = 0.f, SS = 0.f;
#pragma unroll
        for (int i = 0; i < 8; i++) { S += shs[i]; SS += shss[i]; }
        float mean = S * (1.f / (float)D_);
        float var  = SS * (1.f / (float)D_) - mean * mean;
        mean_sh = mean;
        inv_sh  = rsqrtf(var + EPS_);
    }
    __syncthreads();
    float mean = mean_sh, inv = inv_sh;
    out[base + t]       = (v0 - mean) * inv * g[t]       + be[t];
    out[base + t + 256] = (v1 - mean) * inv * g[t + 256] + be[t + 256];
}

// ---------------- gate: softmax(x @ gw + gb) + per-expert sums ----------------
__global__ void __launch_bounds__(256)
gate_kernel(const float* __restrict__ x, const float* __restrict__ gw,
            const float* __restrict__ gb)
{
    const int warp = (blockIdx.x * blockDim.x + threadIdx.x) >> 5;
    const int lane = threadIdx.x & 31;
    if (warp >= BSROWS) return;
    const float* xr = x + (size_t)warp * D_;
    float a0 = 0.f, a1 = 0.f, a2 = 0.f, a3 = 0.f;
    for (int d = lane; d < D_; d += 32) {
        float xv = xr[d];
        const float* wr = gw + (size_t)d * E_;
        a0 += xv * wr[0]; a1 += xv * wr[1]; a2 += xv * wr[2]; a3 += xv * wr[3];
    }
#pragma unroll
    for (int off = 16; off; off >>= 1) {
        a0 += __shfl_down_sync(0xffffffffu, a0, off);
        a1 += __shfl_down_sync(0xffffffffu, a1, off);
        a2 += __shfl_down_sync(0xffffffffu, a2, off);
        a3 += __shfl_down_sync(0xffffffffu, a3, off);
    }
    if (lane == 0) {
        float l0 = a0 + gb[0], l1 = a1 + gb[1], l2 = a2 + gb[2], l3 = a3 + gb[3];
        float mx = fmaxf(fmaxf(l0, l1), fmaxf(l2, l3));
        float e0 = __expf(l0 - mx), e1 = __expf(l1 - mx);
        float e2 = __expf(l2 - mx), e3 = __expf(l3 - mx);
        float si = 1.f / (e0 + e1 + e2 + e3);
        float p0 = e0 * si, p1 = e1 * si, p2 = e2 * si, p3 = e3 * si;
        float* gp = g_gates + (size_t)warp * E_;
        gp[0] = p0; gp[1] = p1; gp[2] = p2; gp[3] = p3;
        atomicAdd(&g_gsum[0], p0);
        atomicAdd(&g_gsum[1], p1);
        atomicAdd(&g_gsum[2], p2);
        atomicAdd(&g_gsum[3], p3);
    }
}

// ---------------- host orchestration ----------------
extern "C" void kernel_launch(void* const* d_in, const int* in_sizes, int n_in,
                              void* d_out, int out_size)
{
    const float* x      = (const float*)d_in[0];
    const float* cross  = (const float*)d_in[1];
    const float* sa_wq  = (const float*)d_in[2];
    const float* sa_bq  = (const float*)d_in[3];
    const float* sa_wk  = (const float*)d_in[4];
    const float* sa_bk  = (const float*)d_in[5];
    const float* sa_wv  = (const float*)d_in[6];
    const float* sa_bv  = (const float*)d_in[7];
    const float* sa_wo  = (const float*)d_in[8];
    const float* sa_bo  = (const float*)d_in[9];
    const float* ca_wq  = (const float*)d_in[10];
    const float* ca_bq  = (const float*)d_in[11];
    const float* ca_wk  = (const float*)d_in[12];
    const float* ca_bk  = (const float*)d_in[13];
    const float* ca_wv  = (const float*)d_in[14];
    const float* ca_bv  = (const float*)d_in[15];
    const float* ca_wo  = (const float*)d_in[16];
    const float* ca_bo  = (const float*)d_in[17];
    const float* gate_w = (const float*)d_in[18];
    const float* gate_b = (const float*)d_in[19];
    const float* exp_w1 = (const float*)d_in[20];
    const float* exp_b1 = (const float*)d_in[21];
    const float* exp_w2 = (const float*)d_in[22];
    const float* exp_b2 = (const float*)d_in[23];
    const float* n1_g   = (const float*)d_in[24];
    const float* n1_b   = (const float*)d_in[25];
    const float* n2_g   = (const float*)d_in[26];
    const float* n2_b   = (const float*)d_in[27];
    const float* n3_g   = (const float*)d_in[28];
    const float* n3_b   = (const float*)d_in[29];
    float* out = (float*)d_out;

    float *qkv, *pre, *xa, *xb, *y, *gates, *bqkv, *bcakv, *b1p;
    __nv_bfloat16 *attbf, *xabf, *xbbf, *hbf, *xbf, *crbf;
    __nv_bfloat16 *wqkvt, *wsaot, *wcaqt, *wcakvt, *wcaot, *w1t, *w2t;
    cudaGetSymbolAddress((void**)&qkv,    g_qkv);
    cudaGetSymbolAddress((void**)&pre,    g_pre);
    cudaGetSymbolAddress((void**)&xa,     g_xa);
    cudaGetSymbolAddress((void**)&xb,     g_xb);
    cudaGetSymbolAddress((void**)&y,      g_y);
    cudaGetSymbolAddress((void**)&gates,  g_gates);
    cudaGetSymbolAddress((void**)&bqkv,   g_bqkv);
    cudaGetSymbolAddress((void**)&bcakv,  g_bcakv);
    cudaGetSymbolAddress((void**)&b1p,    g_b1p);
    cudaGetSymbolAddress((void**)&attbf,  g_attbf);
    cudaGetSymbolAddress((void**)&xabf,   g_xabf);
    cudaGetSymbolAddress((void**)&xbbf,   g_xbbf);
    cudaGetSymbolAddress((void**)&hbf,    g_hbf);
    cudaGetSymbolAddress((void**)&xbf,    g_xbf);
    cudaGetSymbolAddress((void**)&crbf,   g_crbf);
    cudaGetSymbolAddress((void**)&wqkvt,  g_wqkvt);
    cudaGetSymbolAddress((void**)&wsaot,  g_wsaot);
    cudaGetSymbolAddress((void**)&wcaqt,  g_wcaqt);
    cudaGetSymbolAddress((void**)&wcakvt, g_wcakvt);
    cudaGetSymbolAddress((void**)&wcaot,  g_wcaot);
    cudaGetSymbolAddress((void**)&w1t,    g_w1t);
    cudaGetSymbolAddress((void**)&w2t,    g_w2t);

    static bool attr_done = false;
    if (!attr_done) {
        cudaFuncSetAttribute(fattn_kernel<true>,
                             cudaFuncAttributeMaxDynamicSharedMemorySize, ATTN_SMEM_BYTES);
        cudaFuncSetAttribute(fattn_kernel<false>,
                             cudaFuncAttributeMaxDynamicSharedMemorySize, ATTN_SMEM_BYTES);
        cudaFuncSetAttribute(bgemm_kernel,
                             cudaFuncAttributeMaxDynamicSharedMemorySize, BG_SMEM_BYTES);
        attr_done = true;
    }

    // ---- weight packing / conversion (each call; deterministic) ----
    dim3 tb(32, 8);
    tpack_kernel<<<dim3(16,16), tb>>>(sa_wq, 512, wqkvt, 512, 0,    0);
    tpack_kernel<<<dim3(16,16), tb>>>(sa_wk, 512, wqkvt, 512, 512,  0);
    tpack_kernel<<<dim3(16,16), tb>>>(sa_wv, 512, wqkvt, 512, 1024, 0);
    tpack_kernel<<<dim3(16,16), tb>>>(sa_wo, 512, wsaot, 512, 0, 0);
    tpack_kernel<<<dim3(16,16), tb>>>(ca_wq, 512, wcaqt, 512, 0, 0);
    tpack_kernel<<<dim3(16,16), tb>>>(ca_wk, 512, wcakvt, 512, 0,   0);
    tpack_kernel<<<dim3(16,16), tb>>>(ca_wv, 512, wcakvt, 512, 512, 0);
    tpack_kernel<<<dim3(16,16), tb>>>(ca_wo, 512, wcaot, 512, 0, 0);
    for (int e = 0; e < E_; e++) {
        tpack_kernel<<<dim3(64,16), tb>>>(exp_w1 + (size_t)e * D_ * DF_, DF_,
                                          w1t, 512, e * DF_, 0);
        tpack_kernel<<<dim3(16,64), tb>>>(exp_w2 + (size_t)e * DF_ * D_, D_,
                                          w2t, 8192, 0, e * DF_);
        copyf_kernel<<<DF_/256, 256>>>(exp_b1 + (size_t)e * DF_, b1p + e * DF_, DF_);
    }
    copyf_kernel<<<2, 256>>>(sa_bq, bqkv, 512);
    copyf_kernel<<<2, 256>>>(sa_bk, bqkv + 512, 512);
    copyf_kernel<<<2, 256>>>(sa_bv, bqkv + 1024, 512);
    copyf_kernel<<<2, 256>>>(ca_bk, bcakv, 512);
    copyf_kernel<<<2, 256>>>(ca_bv, bcakv + 512, 512);
    cvtbf_kernel<<<(BSROWS*D_/4 + 255)/256, 256>>>(x, xbf, BSROWS*D_/4);
    cvtbf_kernel<<<(BTROWS*D_/4 + 255)/256, 256>>>(cross, crbf, BTROWS*D_/4);

    zero_gsum_kernel<<<1, 32>>>();

    // ---- self-attention block ----
    bgemm(xbf, 512, wqkvt, 512, bqkv, nullptr, nullptr, qkv, nullptr, 1536,
          BSROWS, 1536, FLAG_WF32);
    fattn_kernel<true><<<dim3(S_/64, H_, B_), 128, ATTN_SMEM_BYTES>>>(
        qkv, 1536, qkv + 512, qkv + 1024, 1536, attbf, S_);
    bgemm(attbf, 512, wsaot, 512, sa_bo, /*res=*/x, nullptr, pre, nullptr, 512,
          BSROWS, 512, FLAG_WF32);
    ln_kernel<<<BSROWS, 256>>>(pre, n1_g, n1_b, xa, xabf);

    // ---- cross-attention block ----
    float* qc  = qkv;                         // [16384][512]
    float* kvc = qkv + (size_t)BSROWS * 512;  // [8192][1024]
    bgemm(xabf, 512, wcaqt, 512, ca_bq, nullptr, nullptr, qc, nullptr, 512,
          BSROWS, 512, FLAG_WF32);
    bgemm(crbf, 512, wcakvt, 512, bcakv, nullptr, nullptr, kvc, nullptr, 1024,
          BTROWS, 1024, FLAG_WF32);
    fattn_kernel<false><<<dim3(S_/64, H_, B_), 128, ATTN_SMEM_BYTES>>>(
        qc, 512, kvc, kvc + 512, 1024, attbf, T_);
    bgemm(attbf, 512, wcaot, 512, ca_bo, /*res=*/xa, nullptr, pre, nullptr, 512,
          BSROWS, 512, FLAG_WF32);
    ln_kernel<<<BSROWS, 256>>>(pre, n2_g, n2_b, xb, xbbf);

    // ---- MoE ----
    gate_kernel<<<(BSROWS * 32 + 255) / 256, 256>>>(xb, gate_w, gate_b);
    aux_kernel<<<1, 1>>>(out, out_size);
    // h = relu(xb @ W1 + b1) * gate  (all experts in one GEMM, bf16 out only)
    bgemm(xbbf, 512, w1t, 512, b1p, nullptr, gates, nullptr, hbf, 8192,
          BSROWS, 8192, FLAG_RELU | FLAG_GATE | FLAG_WBF16);
    // y = h @ W2stacked   (K = 8192)
    bgemm(hbf, 8192, w2t, 8192, nullptr, nullptr, nullptr, y, nullptr, 512,
          BSROWS, 512, FLAG_WF32);
    ln3_kernel<<<BSROWS, 256>>>(xb, y, gates, exp_b2, n3_g, n3_b, out);
}

// round 8
// speedup vs baseline: 5.3513x; 1.1191x over previous
#include <cuda_runtime.h>
#include <cuda_bf16.h>
#include <cstdint>

// Problem constants
#define B_  16
#define S_  1024
#define T_  512
#define D_  512
#define H_  8
#define DH_ 64
#define DF_ 2048
#define E_  4
#define BSROWS (B_*S_)    // 16384
#define BTROWS (B_*T_)    // 8192
#define EPS_ 1e-5f

// ---------------- scratch (static __device__ — no allocation) ----------------
__device__ float          g_qkv  [BSROWS*1536];
__device__ __nv_bfloat16  g_attbf[BSROWS*D_];
__device__ float          g_pre  [BSROWS*D_];
__device__ float          g_xa   [BSROWS*D_];
__device__ __nv_bfloat16  g_xabf [BSROWS*D_];
__device__ float          g_xb   [BSROWS*D_];
__device__ __nv_bfloat16  g_xbbf [BSROWS*D_];
__device__ float          g_y    [BSROWS*D_];
__device__ __nv_bfloat16  g_hbf  [(size_t)BSROWS*E_*DF_];
__device__ __nv_bfloat16  g_xbf  [BSROWS*D_];
__device__ __nv_bfloat16  g_crbf [BTROWS*D_];
__device__ float          g_gates[BSROWS*E_];
__device__ float          g_gsum [E_];
// packed / transposed weights (bf16, [N][K] k-contiguous)
__device__ __nv_bfloat16  g_wqkvt [1536*D_];
__device__ float          g_bqkv  [1536];
__device__ __nv_bfloat16  g_wsaot [D_*D_];
__device__ __nv_bfloat16  g_wcaqt [D_*D_];
__device__ __nv_bfloat16  g_wcakvt[1024*D_];
__device__ float          g_bcakv [1024];
__device__ __nv_bfloat16  g_wcaot [D_*D_];
__device__ __nv_bfloat16  g_w1t   [(size_t)E_*DF_*D_];      // [8192][512]
__device__ __nv_bfloat16  g_w2t   [(size_t)D_*E_*DF_];      // [512][8192]

// ---------------- tiny utility kernels ----------------
__global__ void zero_gsum_kernel() {
    if (threadIdx.x < E_) g_gsum[threadIdx.x] = 0.f;
}

__global__ void aux_kernel(float* out, int out_size) {
    float s = 0.f;
#pragma unroll
    for (int e = 0; e < E_; e++) {
        float mn = g_gsum[e] * (1.f / (float)BSROWS);
        s += mn * mn;
    }
    if (out_size > BSROWS * D_) out[BSROWS * D_] = (float)E_ * s;
}

__global__ void copyf_kernel(const float* __restrict__ s, float* __restrict__ d, int n) {
    int i = blockIdx.x * blockDim.x + threadIdx.x;
    if (i < n) d[i] = s[i];
}

__global__ void cvtbf_kernel(const float* __restrict__ s, __nv_bfloat16* __restrict__ d, int n4) {
    int i = blockIdx.x * blockDim.x + threadIdx.x;
    if (i < n4) {
        float4 f = ((const float4*)s)[i];
        __nv_bfloat162* dd = (__nv_bfloat162*)d + i * 2;
        dd[0] = __floats2bfloat162_rn(f.x, f.y);
        dd[1] = __floats2bfloat162_rn(f.z, f.w);
    }
}

// transpose-pack with expert (z) batching:
// dst[(dRow0 + z*zRowStep + c)*dstLd + dCol0 + z*zColStep + r] = bf16(src[z*srcZ + r*srcCols + c])
__global__ void tpack3_kernel(const float* __restrict__ src, int srcCols, size_t srcZ,
                              __nv_bfloat16* __restrict__ dst, int dstLd,
                              int dRow0, int dCol0, int zRowStep, int zColStep)
{
    __shared__ float t[32][33];
    const int z = blockIdx.z;
    const int c0 = blockIdx.x * 32, r0 = blockIdx.y * 32;
    const float* s = src + (size_t)z * srcZ;
    const int row0 = dRow0 + z * zRowStep;
    const int col0 = dCol0 + z * zColStep;
#pragma unroll
    for (int i = 0; i < 4; i++) {
        int rr = threadIdx.y + i * 8;
        t[rr][threadIdx.x] = s[(size_t)(r0 + rr) * srcCols + c0 + threadIdx.x];
    }
    __syncthreads();
#pragma unroll
    for (int i = 0; i < 4; i++) {
        int rr = threadIdx.y + i * 8;
        dst[(size_t)(row0 + c0 + rr) * dstLd + col0 + r0 + threadIdx.x] =
            __float2bfloat16_rn(t[threadIdx.x][rr]);
    }
}

// ---------------- ptx helpers ----------------
__device__ __forceinline__ uint32_t f2tf32(float f) {
    uint32_t u;
    asm volatile("cvt.rna.tf32.f32 %0, %1;\n" : "=r"(u) : "f"(f));
    return u;
}
__device__ __forceinline__ void cp16(void* smem, const void* gmem) {
    uint32_t s = (uint32_t)__cvta_generic_to_shared(smem);
    asm volatile("cp.async.cg.shared.global [%0], [%1], 16;\n" :: "r"(s), "l"(gmem));
}
__device__ __forceinline__ void cp16s(uint32_t saddr, const void* gmem) {
    asm volatile("cp.async.cg.shared.global [%0], [%1], 16;\n" :: "r"(saddr), "l"(gmem));
}
__device__ __forceinline__ void cp_commit() { asm volatile("cp.async.commit_group;\n"); }
__device__ __forceinline__ void cp_wait0()  { asm volatile("cp.async.wait_group 0;\n"); }
__device__ __forceinline__ void cp_wait1()  { asm volatile("cp.async.wait_group 1;\n"); }

__device__ __forceinline__ void mma_tf32(float c[4], const uint32_t a[4], const uint32_t b[2]) {
    asm volatile(
        "mma.sync.aligned.m16n8k8.row.col.f32.tf32.tf32.f32 "
        "{%0,%1,%2,%3}, {%4,%5,%6,%7}, {%8,%9}, {%0,%1,%2,%3};\n"
        : "+f"(c[0]), "+f"(c[1]), "+f"(c[2]), "+f"(c[3])
        : "r"(a[0]), "r"(a[1]), "r"(a[2]), "r"(a[3]), "r"(b[0]), "r"(b[1]));
}

__device__ __forceinline__ void mma_bf16(float c[4], const uint32_t a[4], const uint32_t b[2]) {
    asm volatile(
        "mma.sync.aligned.m16n8k16.row.col.f32.bf16.bf16.f32 "
        "{%0,%1,%2,%3}, {%4,%5,%6,%7}, {%8,%9}, {%0,%1,%2,%3};\n"
        : "+f"(c[0]), "+f"(c[1]), "+f"(c[2]), "+f"(c[3])
        : "r"(a[0]), "r"(a[1]), "r"(a[2]), "r"(a[3]), "r"(b[0]), "r"(b[1]));
}

__device__ __forceinline__ void ldsm_x4(uint32_t& r0, uint32_t& r1, uint32_t& r2, uint32_t& r3,
                                        uint32_t saddr) {
    asm volatile("ldmatrix.sync.aligned.m8n8.x4.shared.b16 {%0,%1,%2,%3}, [%4];"
                 : "=r"(r0), "=r"(r1), "=r"(r2), "=r"(r3) : "r"(saddr));
}

// ---------------- BF16 tensor-core GEMM (ldmatrix + fused epilogue) ---------
// C[M,N] = epi(A[M,K](bf16,lda) @ W[N,K](bf16)^T + bias)
#define FLAG_RELU  1
#define FLAG_GATE  2
#define FLAG_WF32  4
#define FLAG_WBF16 8

// 128x128x64 tiles, 2-stage cp.async, 8 warps (2x4), warp tile 64x32.
// smem rows: 72 bf16 = 144 B = 9 x 16B  -> ldmatrix + cp.async conflict-free.
#define BG_ROWB   144                  // bytes per smem row
#define BG_ASTG   18432                // bytes per A (or B) stage: 128*144
#define BG_SMEM_BYTES 73728            // 2 stages * (A+B)

__global__ void __launch_bounds__(256)
bgemm_kernel(const __nv_bfloat16* __restrict__ A, int lda,
             const __nv_bfloat16* __restrict__ W, int K,
             const float* __restrict__ bias,
             const float* __restrict__ res,
             const float* __restrict__ gates,
             float* __restrict__ Cf, __nv_bfloat16* __restrict__ Cb,
             int ldc, int N, int flags)
{
    extern __shared__ char smc[];
    const uint32_t sb = (uint32_t)__cvta_generic_to_shared(smc);

    const int tid  = threadIdx.x;
    const int warp = tid >> 5;
    const int lane = tid & 31;
    const int r = lane >> 2;     // 0..7
    const int c = lane & 3;      // 0..3
    const int wm = warp >> 2;    // 0..1
    const int wn = warp & 3;     // 0..3
    const int m0 = blockIdx.y * 128, n0 = blockIdx.x * 128;

    float acc[4][4][4];
#pragma unroll
    for (int i = 0; i < 4; i++)
#pragma unroll
        for (int j = 0; j < 4; j++)
#pragma unroll
            for (int q = 0; q < 4; q++) acc[i][j][q] = 0.f;

    const int ntk = K >> 6;
    const __nv_bfloat16* Abase = A + (size_t)m0 * lda;
    const __nv_bfloat16* Bbase = W + (size_t)n0 * K;

    // ldmatrix per-lane row/half offset (bytes):
    // lanes 0-15 -> rows 0..15 at +0; lanes 16-31 -> rows 0..15 at +16B (k+8)
    const uint32_t lmoff = (uint32_t)(lane & 15) * BG_ROWB + (uint32_t)(lane >> 4) * 16;

#define BG_LOAD(s, t) do {                                                      \
        const uint32_t ab = sb + (s) * BG_ASTG;                                 \
        const uint32_t bb = sb + 2 * BG_ASTG + (s) * BG_ASTG;                   \
        _Pragma("unroll")                                                       \
        for (int i_ = 0; i_ < 4; i_++) {                                        \
            const int ch = tid + i_ * 256;                                      \
            const int row = ch >> 3, c16 = ch & 7;                              \
            cp16s(ab + row * BG_ROWB + c16 * 16,                                \
                  Abase + (size_t)row * lda + (t) * 64 + c16 * 8);              \
            cp16s(bb + row * BG_ROWB + c16 * 16,                                \
                  Bbase + (size_t)row * K + (t) * 64 + c16 * 8);                \
        }                                                                       \
    } while (0)

    BG_LOAD(0, 0); cp_commit();
    if (ntk > 1) { BG_LOAD(1, 1); }
    cp_commit();

    for (int t = 0; t < ntk; t++) {
        cp_wait1();
        __syncthreads();
        const int s = t & 1;
        const uint32_t aS = sb + s * BG_ASTG + (uint32_t)(wm * 64) * BG_ROWB + lmoff;
        const uint32_t bS = sb + 2 * BG_ASTG + s * BG_ASTG + (uint32_t)(wn * 32) * BG_ROWB + lmoff;

#pragma unroll
        for (int ks = 0; ks < 4; ks++) {
            const uint32_t kb = ks * 32;   // 16 bf16 = 32 bytes
            uint32_t af[4][4];
#pragma unroll
            for (int mi = 0; mi < 4; mi++)
                ldsm_x4(af[mi][0], af[mi][1], af[mi][2], af[mi][3],
                        aS + (uint32_t)(mi * 16) * BG_ROWB + kb);
            // B: plain (non-trans) ldmatrix — smem rows are n, elements are k.
            // matrix0: n 0-7 /k 0-7 (b0), matrix1: n 8-15 /k 0-7 (b0),
            // matrix2: n 0-7 /k 8-15 (b1), matrix3: n 8-15 /k 8-15 (b1)
            uint32_t b00, b01, b02, b03, b10, b11, b12, b13;
            ldsm_x4(b00, b01, b02, b03, bS + kb);
            ldsm_x4(b10, b11, b12, b13, bS + 16u * BG_ROWB + kb);
            uint32_t bf4[4][2] = {{b00, b02}, {b01, b03}, {b10, b12}, {b11, b13}};
#pragma unroll
            for (int mi = 0; mi < 4; mi++)
#pragma unroll
                for (int nj = 0; nj < 4; nj++)
                    mma_bf16(acc[mi][nj], af[mi], bf4[nj]);
        }
        __syncthreads();
        if (t + 2 < ntk) { BG_LOAD(s, t + 2); }
        cp_commit();
    }

    // ---------------- epilogue ----------------
    const bool do_relu = (flags & FLAG_RELU) != 0;
    const bool do_gate = (flags & FLAG_GATE) != 0;
    const bool wf32    = (flags & FLAG_WF32) != 0;
    const bool wbf16   = (flags & FLAG_WBF16) != 0;
    const int  eblk    = n0 >> 11;

#pragma unroll
    for (int mi = 0; mi < 4; mi++) {
#pragma unroll
        for (int half = 0; half < 2; half++) {
            const int mrow = m0 + wm * 64 + mi * 16 + r + half * 8;
            const float rsv = do_gate ? gates[(size_t)mrow * E_ + eblk] : 1.f;
            const size_t rowbase = (size_t)mrow * ldc;
#pragma unroll
            for (int nj = 0; nj < 4; nj++) {
                const int ncol = n0 + wn * 32 + nj * 8 + 2 * c;
                float v0 = acc[mi][nj][half * 2 + 0];
                float v1 = acc[mi][nj][half * 2 + 1];
                if (bias) { v0 += bias[ncol]; v1 += bias[ncol + 1]; }
                if (do_relu) { v0 = fmaxf(v0, 0.f); v1 = fmaxf(v1, 0.f); }
                v0 *= rsv; v1 *= rsv;
                if (res) { v0 += res[rowbase + ncol]; v1 += res[rowbase + ncol + 1]; }
                if (wf32)  *(float2*)&Cf[rowbase + ncol] = make_float2(v0, v1);
                if (wbf16) *(__nv_bfloat162*)&Cb[rowbase + ncol] = __floats2bfloat162_rn(v0, v1);
            }
        }
    }
#undef BG_LOAD
}

static inline void bgemm(const __nv_bfloat16* A, int lda, const __nv_bfloat16* W, int K,
                         const float* bias, const float* res, const float* gates,
                         float* Cf, __nv_bfloat16* Cb, int ldc, int M, int N, int flags)
{
    dim3 grid(N / 128, M / 128);
    bgemm_kernel<<<grid, 256, BG_SMEM_BYTES>>>(A, lda, W, K, bias, res, gates, Cf, Cb, ldc, N, flags);
}

// ---------------- tensor-core flash attention (tf32 mma, online softmax) ----
#define KS_OFF 0
#define KS_STR 68
#define VS_OFF 4352
#define VS_STR 72
#define PQ_OFF 8960
#define QS_STR 68
#define PS_STR 76
#define PS_WARP 1216
#define ATTN_SMEM_BYTES  55296

template<bool CAUSAL>
__global__ void __launch_bounds__(128)
fattn_kernel(const float* __restrict__ Q, int q_ld,
             const float* __restrict__ Kp, const float* __restrict__ Vp, int kv_ld,
             __nv_bfloat16* __restrict__ Ob, int Sk)
{
    extern __shared__ float smf[];
    uint32_t* smu = (uint32_t*)smf;

    const int b = blockIdx.z, head = blockIdx.y, qt = blockIdx.x;
    const int tid  = threadIdx.x;
    const int w    = tid >> 5;
    const int lane = tid & 31;
    const int r = lane >> 2;
    const int c = lane & 3;
    const int wbase = w * 16;

    const float* Qg = Q + ((size_t)b * S_ + qt * 64) * q_ld + head * DH_;
#pragma unroll
    for (int i = 0; i < 8; i++) {
        const int idx = i * 128 + tid;
        const int row = idx >> 4;
        const int c4  = (idx & 15) * 4;
        *(float4*)&smf[PQ_OFF + row * QS_STR + c4] =
            *(const float4*)(Qg + (size_t)row * q_ld + c4);
    }
    __syncthreads();

    uint32_t aq[8][4];
#pragma unroll
    for (int kt = 0; kt < 8; kt++) {
        aq[kt][0] = f2tf32(0.125f * smf[PQ_OFF + (wbase + r)     * QS_STR + kt * 8 + c]);
        aq[kt][1] = f2tf32(0.125f * smf[PQ_OFF + (wbase + r + 8) * QS_STR + kt * 8 + c]);
        aq[kt][2] = f2tf32(0.125f * smf[PQ_OFF + (wbase + r)     * QS_STR + kt * 8 + c + 4]);
        aq[kt][3] = f2tf32(0.125f * smf[PQ_OFF + (wbase + r + 8) * QS_STR + kt * 8 + c + 4]);
    }

    float accO[8][4];
#pragma unroll
    for (int nj = 0; nj < 8; nj++)
#pragma unroll
        for (int q = 0; q < 4; q++) accO[nj][q] = 0.f;
    float mrow[2] = {-1e30f, -1e30f};
    float lrow[2] = {0.f, 0.f};

    const int ntiles = CAUSAL ? (qt + 1) : (Sk >> 6);

    for (int t = 0; t < ntiles; t++) {
        __syncthreads();

        const float* Kg = Kp + ((size_t)b * Sk + t * 64) * kv_ld + head * DH_;
        const float* Vg = Vp + ((size_t)b * Sk + t * 64) * kv_ld + head * DH_;
#pragma unroll
        for (int i = 0; i < 8; i++) {
            const int idx = i * 128 + tid;
            const int row = idx >> 4;
            const int c4  = (idx & 15) * 4;
            cp16(&smf[KS_OFF + row * KS_STR + c4], Kg + (size_t)row * kv_ld + c4);
            cp16(&smf[VS_OFF + row * VS_STR + c4], Vg + (size_t)row * kv_ld + c4);
        }
        cp_commit();
        cp_wait0();
        __syncthreads();

#pragma unroll
        for (int i = 0; i < 18; i++) {
            const int v4 = i * 128 + tid;
            if (v4 < 2240) {
                float4 f = *(float4*)&smf[v4 * 4];
                uint4 u = make_uint4(f2tf32(f.x), f2tf32(f.y), f2tf32(f.z), f2tf32(f.w));
                *(uint4*)&smu[v4 * 4] = u;
            }
        }
        __syncthreads();

        float accS[8][4];
#pragma unroll
        for (int nj = 0; nj < 8; nj++)
#pragma unroll
            for (int q = 0; q < 4; q++) accS[nj][q] = 0.f;
#pragma unroll
        for (int kt = 0; kt < 8; kt++) {
#pragma unroll
            for (int nj = 0; nj < 8; nj++) {
                uint32_t bv[2];
                bv[0] = smu[KS_OFF + (nj * 8 + r) * KS_STR + kt * 8 + c];
                bv[1] = smu[KS_OFF + (nj * 8 + r) * KS_STR + kt * 8 + c + 4];
                mma_tf32(accS[nj], aq[kt], bv);
            }
        }

        if (CAUSAL && t == qt) {
#pragma unroll
            for (int nj = 0; nj < 8; nj++) {
                const int key0 = nj * 8 + 2 * c;
#pragma unroll
                for (int q = 0; q < 4; q++) {
                    const int key  = key0 + (q & 1);
                    const int qrow = wbase + r + (q >> 1) * 8;
                    if (key > qrow) accS[nj][q] = -1e30f;
                }
            }
        }

#pragma unroll
        for (int hh = 0; hh < 2; hh++) {
            float vmax = -1e30f;
#pragma unroll
            for (int nj = 0; nj < 8; nj++)
                vmax = fmaxf(vmax, fmaxf(accS[nj][2 * hh], accS[nj][2 * hh + 1]));
            vmax = fmaxf(vmax, __shfl_xor_sync(0xffffffffu, vmax, 1));
            vmax = fmaxf(vmax, __shfl_xor_sync(0xffffffffu, vmax, 2));
            const float mnew = fmaxf(mrow[hh], vmax);
            const float corr = __expf(mrow[hh] - mnew);
            float psum = 0.f;
            uint32_t* Pw = smu + PQ_OFF + w * PS_WARP + (r + 8 * hh) * PS_STR + 2 * c;
#pragma unroll
            for (int nj = 0; nj < 8; nj++) {
                const float p0 = __expf(accS[nj][2 * hh]     - mnew);
                const float p1 = __expf(accS[nj][2 * hh + 1] - mnew);
                psum += p0 + p1;
                *(uint2*)&Pw[nj * 8] = make_uint2(f2tf32(p0), f2tf32(p1));
                accO[nj][2 * hh]     *= corr;
                accO[nj][2 * hh + 1] *= corr;
            }
            psum += __shfl_xor_sync(0xffffffffu, psum, 1);
            psum += __shfl_xor_sync(0xffffffffu, psum, 2);
            lrow[hh] = lrow[hh] * corr + psum;
            mrow[hh] = mnew;
        }
        __syncwarp();

        const uint32_t* Pb = smu + PQ_OFF + w * PS_WARP;
#pragma unroll
        for (int kt = 0; kt < 8; kt++) {
            uint32_t ap[4];
            ap[0] = Pb[r       * PS_STR + kt * 8 + c];
            ap[1] = Pb[(r + 8) * PS_STR + kt * 8 + c];
            ap[2] = Pb[r       * PS_STR + kt * 8 + c + 4];
            ap[3] = Pb[(r + 8) * PS_STR + kt * 8 + c + 4];
#pragma unroll
            for (int nj = 0; nj < 8; nj++) {
                uint32_t bv[2];
                bv[0] = smu[VS_OFF + (kt * 8 + c)     * VS_STR + nj * 8 + r];
                bv[1] = smu[VS_OFF + (kt * 8 + c + 4) * VS_STR + nj * 8 + r];
                mma_tf32(accO[nj], ap, bv);
            }
        }
    }

    const float inv0 = 1.f / lrow[0];
    const float inv1 = 1.f / lrow[1];
    const int row0 = qt * 64 + wbase + r;
    __nv_bfloat16* Obp = Ob + ((size_t)b * S_ + row0) * D_ + head * DH_;
#pragma unroll
    for (int nj = 0; nj < 8; nj++) {
        const int col = nj * 8 + 2 * c;
        *(__nv_bfloat162*)&Obp[col] = __floats2bfloat162_rn(accO[nj][0] * inv0, accO[nj][1] * inv0);
        *(__nv_bfloat162*)&Obp[(size_t)8 * D_ + col] =
            __floats2bfloat162_rn(accO[nj][2] * inv1, accO[nj][3] * inv1);
    }
}

// ---------------- LayerNorm kernels ----------------
__global__ void __launch_bounds__(256)
ln_kernel(const float* __restrict__ a,
          const float* __restrict__ g, const float* __restrict__ be,
          float* __restrict__ out, __nv_bfloat16* __restrict__ outb)
{
    const int row = blockIdx.x;
    const int t = threadIdx.x;
    const size_t base = (size_t)row * D_;
    float v0 = a[base + t];
    float v1 = a[base + t + 256];

    float s = v0 + v1, ss = v0 * v0 + v1 * v1;
    const int lane = t & 31, w = t >> 5;
    __shared__ float shs[8], shss[8];
#pragma unroll
    for (int off = 16; off; off >>= 1) {
        s  += __shfl_down_sync(0xffffffffu, s,  off);
        ss += __shfl_down_sync(0xffffffffu, ss, off);
    }
    if (lane == 0) { shs[w] = s; shss[w] = ss; }
    __syncthreads();
    __shared__ float mean_sh, inv_sh;
    if (t == 0) {
        float S = 0.f, SS = 0.f;
#pragma unroll
        for (int i = 0; i < 8; i++) { S += shs[i]; SS += shss[i]; }
        float mean = S * (1.f / (float)D_);
        float var  = SS * (1.f / (float)D_) - mean * mean;
        mean_sh = mean;
        inv_sh  = rsqrtf(var + EPS_);
    }
    __syncthreads();
    float mean = mean_sh, inv = inv_sh;
    float o0 = (v0 - mean) * inv * g[t]       + be[t];
    float o1 = (v1 - mean) * inv * g[t + 256] + be[t + 256];
    out[base + t]       = o0;
    out[base + t + 256] = o1;
    if (outb) {
        outb[base + t]       = __float2bfloat16_rn(o0);
        outb[base + t + 256] = __float2bfloat16_rn(o1);
    }
}

__global__ void __launch_bounds__(256)
ln3_kernel(const float* __restrict__ xb, const float* __restrict__ y,
           const float* __restrict__ gates, const float* __restrict__ b2,
           const float* __restrict__ g, const float* __restrict__ be,
           float* __restrict__ out)
{
    const int row = blockIdx.x;
    const int t = threadIdx.x;
    const size_t base = (size_t)row * D_;
    const float ga0 = gates[(size_t)row * E_ + 0];
    const float ga1 = gates[(size_t)row * E_ + 1];
    const float ga2 = gates[(size_t)row * E_ + 2];
    const float ga3 = gates[(size_t)row * E_ + 3];
    float gb0 = ga0 * b2[t]        + ga1 * b2[D_ + t]        + ga2 * b2[2*D_ + t]        + ga3 * b2[3*D_ + t];
    float gb1 = ga0 * b2[t + 256]  + ga1 * b2[D_ + t + 256]  + ga2 * b2[2*D_ + t + 256]  + ga3 * b2[3*D_ + t + 256];
    float v0 = xb[base + t]       + y[base + t]       + gb0;
    float v1 = xb[base + t + 256] + y[base + t + 256] + gb1;

    float s = v0 + v1, ss = v0 * v0 + v1 * v1;
    const int lane = t & 31, w = t >> 5;
    __shared__ float shs[8], shss[8];
#pragma unroll
    for (int off = 16; off; off >>= 1) {
        s  += __shfl_down_sync(0xffffffffu, s,  off);
        ss += __shfl_down_sync(0xffffffffu, ss, off);
    }
    if (lane == 0) { shs[w] = s; shss[w] = ss; }
    __syncthreads();
    __shared__ float mean_sh, inv_sh;
    if (t == 0) {
        float S = 0.f, SS = 0.f;
#pragma unroll
        for (int i = 0; i < 8; i++) { S += shs[i]; SS += shss[i]; }
        float mean = S * (1.f / (float)D_);
        float var  = SS * (1.f / (float)D_) - mean * mean;
        mean_sh = mean;
        inv_sh  = rsqrtf(var + EPS_);
    }
    __syncthreads();
    float mean = mean_sh, inv = inv_sh;
    out[base + t]       = (v0 - mean) * inv * g[t]       + be[t];
    out[base + t + 256] = (v1 - mean) * inv * g[t + 256] + be[t + 256];
}

// ---------------- gate ----------------
__global__ void __launch_bounds__(256)
gate_kernel(const float* __restrict__ x, const float* __restrict__ gw,
            const float* __restrict__ gb)
{
    const int warp = (blockIdx.x * blockDim.x + threadIdx.x) >> 5;
    const int lane = threadIdx.x & 31;
    if (warp >= BSROWS) return;
    const float* xr = x + (size_t)warp * D_;
    float a0 = 0.f, a1 = 0.f, a2 = 0.f, a3 = 0.f;
    for (int d = lane; d < D_; d += 32) {
        float xv = xr[d];
        const float* wr = gw + (size_t)d * E_;
        a0 += xv * wr[0]; a1 += xv * wr[1]; a2 += xv * wr[2]; a3 += xv * wr[3];
    }
#pragma unroll
    for (int off = 16; off; off >>= 1) {
        a0 += __shfl_down_sync(0xffffffffu, a0, off);
        a1 += __shfl_down_sync(0xffffffffu, a1, off);
        a2 += __shfl_down_sync(0xffffffffu, a2, off);
        a3 += __shfl_down_sync(0xffffffffu, a3, off);
    }
    if (lane == 0) {
        float l0 = a0 + gb[0], l1 = a1 + gb[1], l2 = a2 + gb[2], l3 = a3 + gb[3];
        float mx = fmaxf(fmaxf(l0, l1), fmaxf(l2, l3));
        float e0 = __expf(l0 - mx), e1 = __expf(l1 - mx);
        float e2 = __expf(l2 - mx), e3 = __expf(l3 - mx);
        float si = 1.f / (e0 + e1 + e2 + e3);
        float p0 = e0 * si, p1 = e1 * si, p2 = e2 * si, p3 = e3 * si;
        float* gp = g_gates + (size_t)warp * E_;
        gp[0] = p0; gp[1] = p1; gp[2] = p2; gp[3] = p3;
        atomicAdd(&g_gsum[0], p0);
        atomicAdd(&g_gsum[1], p1);
        atomicAdd(&g_gsum[2], p2);
        atomicAdd(&g_gsum[3], p3);
    }
}

// ---------------- host orchestration ----------------
extern "C" void kernel_launch(void* const* d_in, const int* in_sizes, int n_in,
                              void* d_out, int out_size)
{
    const float* x      = (const float*)d_in[0];
    const float* cross  = (const float*)d_in[1];
    const float* sa_wq  = (const float*)d_in[2];
    const float* sa_bq  = (const float*)d_in[3];
    const float* sa_wk  = (const float*)d_in[4];
    const float* sa_bk  = (const float*)d_in[5];
    const float* sa_wv  = (const float*)d_in[6];
    const float* sa_bv  = (const float*)d_in[7];
    const float* sa_wo  = (const float*)d_in[8];
    const float* sa_bo  = (const float*)d_in[9];
    const float* ca_wq  = (const float*)d_in[10];
    const float* ca_bq  = (const float*)d_in[11];
    const float* ca_wk  = (const float*)d_in[12];
    const float* ca_bk  = (const float*)d_in[13];
    const float* ca_wv  = (const float*)d_in[14];
    const float* ca_bv  = (const float*)d_in[15];
    const float* ca_wo  = (const float*)d_in[16];
    const float* ca_bo  = (const float*)d_in[17];
    const float* gate_w = (const float*)d_in[18];
    const float* gate_b = (const float*)d_in[19];
    const float* exp_w1 = (const float*)d_in[20];
    const float* exp_b1 = (const float*)d_in[21];
    const float* exp_w2 = (const float*)d_in[22];
    const float* exp_b2 = (const float*)d_in[23];
    const float* n1_g   = (const float*)d_in[24];
    const float* n1_b   = (const float*)d_in[25];
    const float* n2_g   = (const float*)d_in[26];
    const float* n2_b   = (const float*)d_in[27];
    const float* n3_g   = (const float*)d_in[28];
    const float* n3_b   = (const float*)d_in[29];
    float* out = (float*)d_out;

    float *qkv, *pre, *xa, *xb, *y, *gates, *bqkv, *bcakv;
    __nv_bfloat16 *attbf, *xabf, *xbbf, *hbf, *xbf, *crbf;
    __nv_bfloat16 *wqkvt, *wsaot, *wcaqt, *wcakvt, *wcaot, *w1t, *w2t;
    cudaGetSymbolAddress((void**)&qkv,    g_qkv);
    cudaGetSymbolAddress((void**)&pre,    g_pre);
    cudaGetSymbolAddress((void**)&xa,     g_xa);
    cudaGetSymbolAddress((void**)&xb,     g_xb);
    cudaGetSymbolAddress((void**)&y,      g_y);
    cudaGetSymbolAddress((void**)&gates,  g_gates);
    cudaGetSymbolAddress((void**)&bqkv,   g_bqkv);
    cudaGetSymbolAddress((void**)&bcakv,  g_bcakv);
    cudaGetSymbolAddress((void**)&attbf,  g_attbf);
    cudaGetSymbolAddress((void**)&xabf,   g_xabf);
    cudaGetSymbolAddress((void**)&xbbf,   g_xbbf);
    cudaGetSymbolAddress((void**)&hbf,    g_hbf);
    cudaGetSymbolAddress((void**)&xbf,    g_xbf);
    cudaGetSymbolAddress((void**)&crbf,   g_crbf);
    cudaGetSymbolAddress((void**)&wqkvt,  g_wqkvt);
    cudaGetSymbolAddress((void**)&wsaot,  g_wsaot);
    cudaGetSymbolAddress((void**)&wcaqt,  g_wcaqt);
    cudaGetSymbolAddress((void**)&wcakvt, g_wcakvt);
    cudaGetSymbolAddress((void**)&wcaot,  g_wcaot);
    cudaGetSymbolAddress((void**)&w1t,    g_w1t);
    cudaGetSymbolAddress((void**)&w2t,    g_w2t);

    static bool attr_done = false;
    if (!attr_done) {
        cudaFuncSetAttribute(fattn_kernel<true>,
                             cudaFuncAttributeMaxDynamicSharedMemorySize, ATTN_SMEM_BYTES);
        cudaFuncSetAttribute(fattn_kernel<false>,
                             cudaFuncAttributeMaxDynamicSharedMemorySize, ATTN_SMEM_BYTES);
        cudaFuncSetAttribute(bgemm_kernel,
                             cudaFuncAttributeMaxDynamicSharedMemorySize, BG_SMEM_BYTES);
        attr_done = true;
    }

    // ---- weight packing / conversion ----
    dim3 tb(32, 8);
    tpack3_kernel<<<dim3(16,16,1), tb>>>(sa_wq, 512, 0, wqkvt, 512, 0,    0, 0, 0);
    tpack3_kernel<<<dim3(16,16,1), tb>>>(sa_wk, 512, 0, wqkvt, 512, 512,  0, 0, 0);
    tpack3_kernel<<<dim3(16,16,1), tb>>>(sa_wv, 512, 0, wqkvt, 512, 1024, 0, 0, 0);
    tpack3_kernel<<<dim3(16,16,1), tb>>>(sa_wo, 512, 0, wsaot, 512, 0, 0, 0, 0);
    tpack3_kernel<<<dim3(16,16,1), tb>>>(ca_wq, 512, 0, wcaqt, 512, 0, 0, 0, 0);
    tpack3_kernel<<<dim3(16,16,1), tb>>>(ca_wk, 512, 0, wcakvt, 512, 0,   0, 0, 0);
    tpack3_kernel<<<dim3(16,16,1), tb>>>(ca_wv, 512, 0, wcakvt, 512, 512, 0, 0, 0);
    tpack3_kernel<<<dim3(16,16,1), tb>>>(ca_wo, 512, 0, wcaot, 512, 0, 0, 0, 0);
    // exp_w1 [E][D][DF] -> w1t [E*DF][D] ; exp_w2 [E][DF][D] -> w2t [D][E*DF]
    tpack3_kernel<<<dim3(64,16,4), tb>>>(exp_w1, DF_, (size_t)D_*DF_, w1t, 512, 0, 0, DF_, 0);
    tpack3_kernel<<<dim3(16,64,4), tb>>>(exp_w2, 512, (size_t)DF_*D_, w2t, 8192, 0, 0, 0, DF_);
    copyf_kernel<<<2, 256>>>(sa_bq, bqkv, 512);
    copyf_kernel<<<2, 256>>>(sa_bk, bqkv + 512, 512);
    copyf_kernel<<<2, 256>>>(sa_bv, bqkv + 1024, 512);
    copyf_kernel<<<2, 256>>>(ca_bk, bcakv, 512);
    copyf_kernel<<<2, 256>>>(ca_bv, bcakv + 512, 512);
    cvtbf_kernel<<<(BSROWS*D_/4 + 255)/256, 256>>>(x, xbf, BSROWS*D_/4);
    cvtbf_kernel<<<(BTROWS*D_/4 + 255)/256, 256>>>(cross, crbf, BTROWS*D_/4);

    zero_gsum_kernel<<<1, 32>>>();

    // ---- self-attention block ----
    bgemm(xbf, 512, wqkvt, 512, bqkv, nullptr, nullptr, qkv, nullptr, 1536,
          BSROWS, 1536, FLAG_WF32);
    fattn_kernel<true><<<dim3(S_/64, H_, B_), 128, ATTN_SMEM_BYTES>>>(
        qkv, 1536, qkv + 512, qkv + 1024, 1536, attbf, S_);
    bgemm(attbf, 512, wsaot, 512, sa_bo, /*res=*/x, nullptr, pre, nullptr, 512,
          BSROWS, 512, FLAG_WF32);
    ln_kernel<<<BSROWS, 256>>>(pre, n1_g, n1_b, xa, xabf);

    // ---- cross-attention block ----
    float* qc  = qkv;
    float* kvc = qkv + (size_t)BSROWS * 512;
    bgemm(xabf, 512, wcaqt, 512, ca_bq, nullptr, nullptr, qc, nullptr, 512,
          BSROWS, 512, FLAG_WF32);
    bgemm(crbf, 512, wcakvt, 512, bcakv, nullptr, nullptr, kvc, nullptr, 1024,
          BTROWS, 1024, FLAG_WF32);
    fattn_kernel<false><<<dim3(S_/64, H_, B_), 128, ATTN_SMEM_BYTES>>>(
        qc, 512, kvc, kvc + 512, 1024, attbf, T_);
    bgemm(attbf, 512, wcaot, 512, ca_bo, /*res=*/xa, nullptr, pre, nullptr, 512,
          BSROWS, 512, FLAG_WF32);
    ln_kernel<<<BSROWS, 256>>>(pre, n2_g, n2_b, xb, xbbf);

    // ---- MoE ----
    gate_kernel<<<(BSROWS * 32 + 255) / 256, 256>>>(xb, gate_w, gate_b);
    aux_kernel<<<1, 1>>>(out, out_size);
    // h = relu(xb @ W1 + b1) * gate   (exp_b1 is already the stacked [E*DF] bias)
    bgemm(xbbf, 512, w1t, 512, exp_b1, nullptr, gates, nullptr, hbf, 8192,
          BSROWS, 8192, FLAG_RELU | FLAG_GATE | FLAG_WBF16);
    // y = h @ W2stacked  (K = 8192)
    bgemm(hbf, 8192, w2t, 8192, nullptr, nullptr, nullptr, y, nullptr, 512,
          BSROWS, 512, FLAG_WF32);
    ln3_kernel<<<BSROWS, 256>>>(xb, y, gates, exp_b2, n3_g, n3_b, out);
}

// round 9
// speedup vs baseline: 6.0000x; 1.1212x over previous
#include <cuda_runtime.h>
#include <cuda_bf16.h>
#include <cstdint>

// Problem constants
#define B_  16
#define S_  1024
#define T_  512
#define D_  512
#define H_  8
#define DH_ 64
#define DF_ 2048
#define E_  4
#define BSROWS (B_*S_)    // 16384
#define BTROWS (B_*T_)    // 8192
#define EPS_ 1e-5f

// ---------------- scratch (static __device__ — no allocation) ----------------
__device__ float          g_qkv  [BSROWS*1536];
__device__ __nv_bfloat16  g_attbf[BSROWS*D_];
__device__ float          g_pre  [BSROWS*D_];
__device__ float          g_xa   [BSROWS*D_];
__device__ __nv_bfloat16  g_xabf [BSROWS*D_];
__device__ float          g_xb   [BSROWS*D_];
__device__ __nv_bfloat16  g_xbbf [BSROWS*D_];
__device__ float          g_y    [BSROWS*D_];
__device__ __nv_bfloat16  g_hbf  [(size_t)BSROWS*E_*DF_];
__device__ __nv_bfloat16  g_xbf  [BSROWS*D_];
__device__ __nv_bfloat16  g_crbf [BTROWS*D_];
__device__ float          g_gates[BSROWS*E_];
__device__ float          g_gsum [E_];
// packed / transposed weights (bf16, [N][K] k-contiguous)
__device__ __nv_bfloat16  g_wqkvt [1536*D_];
__device__ float          g_bqkv  [1536];
__device__ __nv_bfloat16  g_wsaot [D_*D_];
__device__ __nv_bfloat16  g_wcaqt [D_*D_];
__device__ __nv_bfloat16  g_wcakvt[1024*D_];
__device__ float          g_bcakv [1024];
__device__ __nv_bfloat16  g_wcaot [D_*D_];
__device__ __nv_bfloat16  g_w1t   [(size_t)E_*DF_*D_];      // [8192][512]
__device__ __nv_bfloat16  g_w2t   [(size_t)D_*E_*DF_];      // [512][8192]

// ---------------- tiny utility kernels ----------------
__global__ void zero_gsum_kernel() {
    if (threadIdx.x < E_) g_gsum[threadIdx.x] = 0.f;
}

__global__ void aux_kernel(float* out, int out_size) {
    float s = 0.f;
#pragma unroll
    for (int e = 0; e < E_; e++) {
        float mn = g_gsum[e] * (1.f / (float)BSROWS);
        s += mn * mn;
    }
    if (out_size > BSROWS * D_) out[BSROWS * D_] = (float)E_ * s;
}

// pack up to 3 bias vectors of 512 into one buffer
__global__ void pack3f_kernel(const float* __restrict__ a, const float* __restrict__ b,
                              const float* __restrict__ c, float* __restrict__ d)
{
    int i = blockIdx.x * blockDim.x + threadIdx.x;
    if (i < 512) {
        d[i] = a[i];
        if (b) d[512 + i]  = b[i];
        if (c) d[1024 + i] = c[i];
    }
}

__global__ void cvtbf_kernel(const float* __restrict__ s, __nv_bfloat16* __restrict__ d, int n4) {
    int i = blockIdx.x * blockDim.x + threadIdx.x;
    if (i < n4) {
        float4 f = ((const float4*)s)[i];
        __nv_bfloat162* dd = (__nv_bfloat162*)d + i * 2;
        dd[0] = __floats2bfloat162_rn(f.x, f.y);
        dd[1] = __floats2bfloat162_rn(f.z, f.w);
    }
}

// transpose-pack with z batching over a single contiguous src:
// dst[(dRow0 + z*zRowStep + c)*dstLd + dCol0 + z*zColStep + r] = bf16(src[z*srcZ + r*srcCols + c])
__global__ void tpack3_kernel(const float* __restrict__ src, int srcCols, size_t srcZ,
                              __nv_bfloat16* __restrict__ dst, int dstLd,
                              int dRow0, int dCol0, int zRowStep, int zColStep)
{
    __shared__ float t[32][33];
    const int z = blockIdx.z;
    const int c0 = blockIdx.x * 32, r0 = blockIdx.y * 32;
    const float* s = src + (size_t)z * srcZ;
    const int row0 = dRow0 + z * zRowStep;
    const int col0 = dCol0 + z * zColStep;
#pragma unroll
    for (int i = 0; i < 4; i++) {
        int rr = threadIdx.y + i * 8;
        t[rr][threadIdx.x] = s[(size_t)(r0 + rr) * srcCols + c0 + threadIdx.x];
    }
    __syncthreads();
#pragma unroll
    for (int i = 0; i < 4; i++) {
        int rr = threadIdx.y + i * 8;
        dst[(size_t)(row0 + c0 + rr) * dstLd + col0 + r0 + threadIdx.x] =
            __float2bfloat16_rn(t[threadIdx.x][rr]);
    }
}

// transpose-pack 3 separate 512x512 sources stacked by z into dst rows z*512..
__global__ void tpackz_kernel(const float* __restrict__ s0, const float* __restrict__ s1,
                              const float* __restrict__ s2,
                              __nv_bfloat16* __restrict__ dst)
{
    __shared__ float t[32][33];
    const int z = blockIdx.z;
    const float* s = (z == 0) ? s0 : (z == 1) ? s1 : s2;
    const int c0 = blockIdx.x * 32, r0 = blockIdx.y * 32;
#pragma unroll
    for (int i = 0; i < 4; i++) {
        int rr = threadIdx.y + i * 8;
        t[rr][threadIdx.x] = s[(size_t)(r0 + rr) * 512 + c0 + threadIdx.x];
    }
    __syncthreads();
#pragma unroll
    for (int i = 0; i < 4; i++) {
        int rr = threadIdx.y + i * 8;
        dst[(size_t)(z * 512 + c0 + rr) * 512 + r0 + threadIdx.x] =
            __float2bfloat16_rn(t[threadIdx.x][rr]);
    }
}

// ---------------- ptx helpers ----------------
__device__ __forceinline__ uint32_t f2tf32(float f) {
    uint32_t u;
    asm volatile("cvt.rna.tf32.f32 %0, %1;\n" : "=r"(u) : "f"(f));
    return u;
}
__device__ __forceinline__ void cp16(void* smem, const void* gmem) {
    uint32_t s = (uint32_t)__cvta_generic_to_shared(smem);
    asm volatile("cp.async.cg.shared.global [%0], [%1], 16;\n" :: "r"(s), "l"(gmem));
}
__device__ __forceinline__ void cp16s(uint32_t saddr, const void* gmem) {
    asm volatile("cp.async.cg.shared.global [%0], [%1], 16;\n" :: "r"(saddr), "l"(gmem));
}
__device__ __forceinline__ void cp_commit() { asm volatile("cp.async.commit_group;\n"); }
__device__ __forceinline__ void cp_wait0()  { asm volatile("cp.async.wait_group 0;\n"); }
__device__ __forceinline__ void cp_wait1()  { asm volatile("cp.async.wait_group 1;\n"); }

__device__ __forceinline__ void mma_tf32(float c[4], const uint32_t a[4], const uint32_t b[2]) {
    asm volatile(
        "mma.sync.aligned.m16n8k8.row.col.f32.tf32.tf32.f32 "
        "{%0,%1,%2,%3}, {%4,%5,%6,%7}, {%8,%9}, {%0,%1,%2,%3};\n"
        : "+f"(c[0]), "+f"(c[1]), "+f"(c[2]), "+f"(c[3])
        : "r"(a[0]), "r"(a[1]), "r"(a[2]), "r"(a[3]), "r"(b[0]), "r"(b[1]));
}

__device__ __forceinline__ void mma_bf16(float c[4], const uint32_t a[4], const uint32_t b[2]) {
    asm volatile(
        "mma.sync.aligned.m16n8k16.row.col.f32.bf16.bf16.f32 "
        "{%0,%1,%2,%3}, {%4,%5,%6,%7}, {%8,%9}, {%0,%1,%2,%3};\n"
        : "+f"(c[0]), "+f"(c[1]), "+f"(c[2]), "+f"(c[3])
        : "r"(a[0]), "r"(a[1]), "r"(a[2]), "r"(a[3]), "r"(b[0]), "r"(b[1]));
}

__device__ __forceinline__ void ldsm_x4(uint32_t& r0, uint32_t& r1, uint32_t& r2, uint32_t& r3,
                                        uint32_t saddr) {
    asm volatile("ldmatrix.sync.aligned.m8n8.x4.shared.b16 {%0,%1,%2,%3}, [%4];"
                 : "=r"(r0), "=r"(r1), "=r"(r2), "=r"(r3) : "r"(saddr));
}

// ---------------- BF16 tensor-core GEMM (ldmatrix + fused epilogue) ---------
// C[M,N] = epi(A[M,K](bf16,lda) @ W[N,K](bf16)^T + bias)
#define FLAG_RELU  1
#define FLAG_GATE  2
#define FLAG_WF32  4
#define FLAG_WBF16 8
#define FLAG_WTF32 16   // round fp32 output to tf32 bit pattern (for attention inputs)

// 128x128x64 tiles, 2-stage cp.async, 8 warps (2x4), warp tile 64x32.
// smem rows: 72 bf16 = 144 B = 9 x 16B  -> ldmatrix + cp.async conflict-free.
#define BG_ROWB   144                  // bytes per smem row
#define BG_ASTG   18432                // bytes per A (or B) stage: 128*144
#define BG_SMEM_BYTES 73728            // 2 stages * (A+B)

__global__ void __launch_bounds__(256)
bgemm_kernel(const __nv_bfloat16* __restrict__ A, int lda,
             const __nv_bfloat16* __restrict__ W, int K,
             const float* __restrict__ bias,
             const float* __restrict__ res,
             const float* __restrict__ gates,
             float* __restrict__ Cf, __nv_bfloat16* __restrict__ Cb,
             int ldc, int N, int flags)
{
    extern __shared__ char smc[];
    const uint32_t sb = (uint32_t)__cvta_generic_to_shared(smc);

    const int tid  = threadIdx.x;
    const int warp = tid >> 5;
    const int lane = tid & 31;
    const int r = lane >> 2;     // 0..7
    const int c = lane & 3;      // 0..3
    const int wm = warp >> 2;    // 0..1
    const int wn = warp & 3;     // 0..3
    const int m0 = blockIdx.y * 128, n0 = blockIdx.x * 128;

    float acc[4][4][4];
#pragma unroll
    for (int i = 0; i < 4; i++)
#pragma unroll
        for (int j = 0; j < 4; j++)
#pragma unroll
            for (int q = 0; q < 4; q++) acc[i][j][q] = 0.f;

    const int ntk = K >> 6;
    const __nv_bfloat16* Abase = A + (size_t)m0 * lda;
    const __nv_bfloat16* Bbase = W + (size_t)n0 * K;

    const uint32_t lmoff = (uint32_t)(lane & 15) * BG_ROWB + (uint32_t)(lane >> 4) * 16;

#define BG_LOAD(s, t) do {                                                      \
        const uint32_t ab = sb + (s) * BG_ASTG;                                 \
        const uint32_t bb = sb + 2 * BG_ASTG + (s) * BG_ASTG;                   \
        _Pragma("unroll")                                                       \
        for (int i_ = 0; i_ < 4; i_++) {                                        \
            const int ch = tid + i_ * 256;                                      \
            const int row = ch >> 3, c16 = ch & 7;                              \
            cp16s(ab + row * BG_ROWB + c16 * 16,                                \
                  Abase + (size_t)row * lda + (t) * 64 + c16 * 8);              \
            cp16s(bb + row * BG_ROWB + c16 * 16,                                \
                  Bbase + (size_t)row * K + (t) * 64 + c16 * 8);                \
        }                                                                       \
    } while (0)

    BG_LOAD(0, 0); cp_commit();
    if (ntk > 1) { BG_LOAD(1, 1); }
    cp_commit();

    for (int t = 0; t < ntk; t++) {
        cp_wait1();
        __syncthreads();
        const int s = t & 1;
        const uint32_t aS = sb + s * BG_ASTG + (uint32_t)(wm * 64) * BG_ROWB + lmoff;
        const uint32_t bS = sb + 2 * BG_ASTG + s * BG_ASTG + (uint32_t)(wn * 32) * BG_ROWB + lmoff;

#pragma unroll
        for (int ks = 0; ks < 4; ks++) {
            const uint32_t kb = ks * 32;   // 16 bf16 = 32 bytes
            uint32_t af[4][4];
#pragma unroll
            for (int mi = 0; mi < 4; mi++)
                ldsm_x4(af[mi][0], af[mi][1], af[mi][2], af[mi][3],
                        aS + (uint32_t)(mi * 16) * BG_ROWB + kb);
            // B: plain (non-trans) ldmatrix — smem rows are n, elements are k.
            uint32_t b00, b01, b02, b03, b10, b11, b12, b13;
            ldsm_x4(b00, b01, b02, b03, bS + kb);
            ldsm_x4(b10, b11, b12, b13, bS + 16u * BG_ROWB + kb);
            uint32_t bf4[4][2] = {{b00, b02}, {b01, b03}, {b10, b12}, {b11, b13}};
#pragma unroll
            for (int mi = 0; mi < 4; mi++)
#pragma unroll
                for (int nj = 0; nj < 4; nj++)
                    mma_bf16(acc[mi][nj], af[mi], bf4[nj]);
        }
        __syncthreads();
        if (t + 2 < ntk) { BG_LOAD(s, t + 2); }
        cp_commit();
    }

    // ---------------- epilogue ----------------
    const bool do_relu = (flags & FLAG_RELU) != 0;
    const bool do_gate = (flags & FLAG_GATE) != 0;
    const bool wf32    = (flags & FLAG_WF32) != 0;
    const bool wbf16   = (flags & FLAG_WBF16) != 0;
    const bool wtf32   = (flags & FLAG_WTF32) != 0;
    const int  eblk    = n0 >> 11;

#pragma unroll
    for (int mi = 0; mi < 4; mi++) {
#pragma unroll
        for (int half = 0; half < 2; half++) {
            const int mrow = m0 + wm * 64 + mi * 16 + r + half * 8;
            const float rsv = do_gate ? gates[(size_t)mrow * E_ + eblk] : 1.f;
            const size_t rowbase = (size_t)mrow * ldc;
#pragma unroll
            for (int nj = 0; nj < 4; nj++) {
                const int ncol = n0 + wn * 32 + nj * 8 + 2 * c;
                float v0 = acc[mi][nj][half * 2 + 0];
                float v1 = acc[mi][nj][half * 2 + 1];
                if (bias) { v0 += bias[ncol]; v1 += bias[ncol + 1]; }
                if (do_relu) { v0 = fmaxf(v0, 0.f); v1 = fmaxf(v1, 0.f); }
                v0 *= rsv; v1 *= rsv;
                if (res) { v0 += res[rowbase + ncol]; v1 += res[rowbase + ncol + 1]; }
                if (wtf32) {
                    v0 = __uint_as_float(f2tf32(v0));
                    v1 = __uint_as_float(f2tf32(v1));
                }
                if (wf32)  *(float2*)&Cf[rowbase + ncol] = make_float2(v0, v1);
                if (wbf16) *(__nv_bfloat162*)&Cb[rowbase + ncol] = __floats2bfloat162_rn(v0, v1);
            }
        }
    }
#undef BG_LOAD
}

static inline void bgemm(const __nv_bfloat16* A, int lda, const __nv_bfloat16* W, int K,
                         const float* bias, const float* res, const float* gates,
                         float* Cf, __nv_bfloat16* Cb, int ldc, int M, int N, int flags)
{
    dim3 grid(N / 128, M / 128);
    bgemm_kernel<<<grid, 256, BG_SMEM_BYTES>>>(A, lda, W, K, bias, res, gates, Cf, Cb, ldc, N, flags);
}

// ---------------- tensor-core flash attention (tf32 mma, online softmax) ----
// Inputs Q/K/V are fp32 values PRE-ROUNDED to tf32 (FLAG_WTF32 in producer GEMM),
// so loaded bit patterns are valid tf32 operands — no conversion pass needed.
// Double-buffered KV tiles: cp.async of tile t+1 overlaps compute of tile t.
#define ATT_STG  8960        // floats per KV stage (K 64x68 + V 64x72)
#define KS_STR 68
#define VS_STR 72
#define PQ_OFF 17920         // Q staging (64x68) / P tiles (4x16x76), floats
#define QS_STR 68
#define PS_STR 76
#define PS_WARP 1216
#define ATTN_SMEM_BYTES 91136   // (17920 + 4864) * 4

template<bool CAUSAL>
__global__ void __launch_bounds__(128)
fattn_kernel(const float* __restrict__ Q, int q_ld,
             const float* __restrict__ Kp, const float* __restrict__ Vp, int kv_ld,
             __nv_bfloat16* __restrict__ Ob, int Sk)
{
    extern __shared__ float smf[];
    uint32_t* smu = (uint32_t*)smf;

    const int b = blockIdx.z, head = blockIdx.y, qt = blockIdx.x;
    const int tid  = threadIdx.x;
    const int w    = tid >> 5;
    const int lane = tid & 31;
    const int r = lane >> 2;
    const int c = lane & 3;
    const int wbase = w * 16;

    // ---- stage Q into smem, build scaled tf32 A-fragments ----
    const float* Qg = Q + ((size_t)b * S_ + qt * 64) * q_ld + head * DH_;
#pragma unroll
    for (int i = 0; i < 8; i++) {
        const int idx = i * 128 + tid;
        const int row = idx >> 4;
        const int c4  = (idx & 15) * 4;
        *(float4*)&smf[PQ_OFF + row * QS_STR + c4] =
            *(const float4*)(Qg + (size_t)row * q_ld + c4);
    }
    __syncthreads();

    uint32_t aq[8][4];
#pragma unroll
    for (int kt = 0; kt < 8; kt++) {
        aq[kt][0] = f2tf32(0.125f * smf[PQ_OFF + (wbase + r)     * QS_STR + kt * 8 + c]);
        aq[kt][1] = f2tf32(0.125f * smf[PQ_OFF + (wbase + r + 8) * QS_STR + kt * 8 + c]);
        aq[kt][2] = f2tf32(0.125f * smf[PQ_OFF + (wbase + r)     * QS_STR + kt * 8 + c + 4]);
        aq[kt][3] = f2tf32(0.125f * smf[PQ_OFF + (wbase + r + 8) * QS_STR + kt * 8 + c + 4]);
    }

    float accO[8][4];
#pragma unroll
    for (int nj = 0; nj < 8; nj++)
#pragma unroll
        for (int q = 0; q < 4; q++) accO[nj][q] = 0.f;
    float mrow[2] = {-1e30f, -1e30f};
    float lrow[2] = {0.f, 0.f};

    const int ntiles = CAUSAL ? (qt + 1) : (Sk >> 6);

    // tile loader into stage s
#define ATT_LOAD(s, t) do {                                                      \
        const float* Kg_ = Kp + ((size_t)b * Sk + (t) * 64) * kv_ld + head * DH_;\
        const float* Vg_ = Vp + ((size_t)b * Sk + (t) * 64) * kv_ld + head * DH_;\
        float* ks_ = smf + (s) * ATT_STG;                                        \
        float* vs_ = smf + (s) * ATT_STG + 4352;                                 \
        _Pragma("unroll")                                                        \
        for (int i_ = 0; i_ < 8; i_++) {                                         \
            const int idx_ = i_ * 128 + tid;                                     \
            const int row_ = idx_ >> 4;                                          \
            const int c4_  = (idx_ & 15) * 4;                                    \
            cp16(ks_ + row_ * KS_STR + c4_, Kg_ + (size_t)row_ * kv_ld + c4_);   \
            cp16(vs_ + row_ * VS_STR + c4_, Vg_ + (size_t)row_ * kv_ld + c4_);   \
        }                                                                        \
    } while (0)

    ATT_LOAD(0, 0);
    cp_commit();

    for (int t = 0; t < ntiles; t++) {
        __syncthreads();   // all warps done with the buffer being overwritten
        if (t + 1 < ntiles) {
            ATT_LOAD((t + 1) & 1, t + 1);
            cp_commit();
            cp_wait1();    // tile t complete
        } else {
            cp_wait0();
        }
        __syncthreads();

        const uint32_t ks0 = (uint32_t)((t & 1) * ATT_STG);
        const uint32_t vs0 = ks0 + 4352;

        // ---- S = Q K^T (operands already tf32-rounded) ----
        float accS[8][4];
#pragma unroll
        for (int nj = 0; nj < 8; nj++)
#pragma unroll
            for (int q = 0; q < 4; q++) accS[nj][q] = 0.f;
#pragma unroll
        for (int kt = 0; kt < 8; kt++) {
#pragma unroll
            for (int nj = 0; nj < 8; nj++) {
                uint32_t bv[2];
                bv[0] = smu[ks0 + (nj * 8 + r) * KS_STR + kt * 8 + c];
                bv[1] = smu[ks0 + (nj * 8 + r) * KS_STR + kt * 8 + c + 4];
                mma_tf32(accS[nj], aq[kt], bv);
            }
        }

        if (CAUSAL && t == qt) {
#pragma unroll
            for (int nj = 0; nj < 8; nj++) {
                const int key0 = nj * 8 + 2 * c;
#pragma unroll
                for (int q = 0; q < 4; q++) {
                    const int key  = key0 + (q & 1);
                    const int qrow = wbase + r + (q >> 1) * 8;
                    if (key > qrow) accS[nj][q] = -1e30f;
                }
            }
        }

        // ---- online softmax ----
#pragma unroll
        for (int hh = 0; hh < 2; hh++) {
            float vmax = -1e30f;
#pragma unroll
            for (int nj = 0; nj < 8; nj++)
                vmax = fmaxf(vmax, fmaxf(accS[nj][2 * hh], accS[nj][2 * hh + 1]));
            vmax = fmaxf(vmax, __shfl_xor_sync(0xffffffffu, vmax, 1));
            vmax = fmaxf(vmax, __shfl_xor_sync(0xffffffffu, vmax, 2));
            const float mnew = fmaxf(mrow[hh], vmax);
            const float corr = __expf(mrow[hh] - mnew);
            float psum = 0.f;
            uint32_t* Pw = smu + PQ_OFF + w * PS_WARP + (r + 8 * hh) * PS_STR + 2 * c;
#pragma unroll
            for (int nj = 0; nj < 8; nj++) {
                const float p0 = __expf(accS[nj][2 * hh]     - mnew);
                const float p1 = __expf(accS[nj][2 * hh + 1] - mnew);
                psum += p0 + p1;
                *(uint2*)&Pw[nj * 8] = make_uint2(f2tf32(p0), f2tf32(p1));
                accO[nj][2 * hh]     *= corr;
                accO[nj][2 * hh + 1] *= corr;
            }
            psum += __shfl_xor_sync(0xffffffffu, psum, 1);
            psum += __shfl_xor_sync(0xffffffffu, psum, 2);
            lrow[hh] = lrow[hh] * corr + psum;
            mrow[hh] = mnew;
        }
        __syncwarp();

        // ---- O += P V ----
        const uint32_t* Pb = smu + PQ_OFF + w * PS_WARP;
#pragma unroll
        for (int kt = 0; kt < 8; kt++) {
            uint32_t ap[4];
            ap[0] = Pb[r       * PS_STR + kt * 8 + c];
            ap[1] = Pb[(r + 8) * PS_STR + kt * 8 + c];
            ap[2] = Pb[r       * PS_STR + kt * 8 + c + 4];
            ap[3] = Pb[(r + 8) * PS_STR + kt * 8 + c + 4];
#pragma unroll
            for (int nj = 0; nj < 8; nj++) {
                uint32_t bv[2];
                bv[0] = smu[vs0 + (kt * 8 + c)     * VS_STR + nj * 8 + r];
                bv[1] = smu[vs0 + (kt * 8 + c + 4) * VS_STR + nj * 8 + r];
                mma_tf32(accO[nj], ap, bv);
            }
        }
    }
#undef ATT_LOAD

    const float inv0 = 1.f / lrow[0];
    const float inv1 = 1.f / lrow[1];
    const int row0 = qt * 64 + wbase + r;
    __nv_bfloat16* Obp = Ob + ((size_t)b * S_ + row0) * D_ + head * DH_;
#pragma unroll
    for (int nj = 0; nj < 8; nj++) {
        const int col = nj * 8 + 2 * c;
        *(__nv_bfloat162*)&Obp[col] = __floats2bfloat162_rn(accO[nj][0] * inv0, accO[nj][1] * inv0);
        *(__nv_bfloat162*)&Obp[(size_t)8 * D_ + col] =
            __floats2bfloat162_rn(accO[nj][2] * inv1, accO[nj][3] * inv1);
    }
}

// ---------------- LayerNorm kernels ----------------
__global__ void __launch_bounds__(256)
ln_kernel(const float* __restrict__ a,
          const float* __restrict__ g, const float* __restrict__ be,
          float* __restrict__ out, __nv_bfloat16* __restrict__ outb)
{
    const int row = blockIdx.x;
    const int t = threadIdx.x;
    const size_t base = (size_t)row * D_;
    float v0 = a[base + t];
    float v1 = a[base + t + 256];

    float s = v0 + v1, ss = v0 * v0 + v1 * v1;
    const int lane = t & 31, w = t >> 5;
    __shared__ float shs[8], shss[8];
#pragma unroll
    for (int off = 16; off; off >>= 1) {
        s  += __shfl_down_sync(0xffffffffu, s,  off);
        ss += __shfl_down_sync(0xffffffffu, ss, off);
    }
    if (lane == 0) { shs[w] = s; shss[w] = ss; }
    __syncthreads();
    __shared__ float mean_sh, inv_sh;
    if (t == 0) {
        float S = 0.f, SS = 0.f;
#pragma unroll
        for (int i = 0; i < 8; i++) { S += shs[i]; SS += shss[i]; }
        float mean = S * (1.f / (float)D_);
        float var  = SS * (1.f / (float)D_) - mean * mean;
        mean_sh = mean;
        inv_sh  = rsqrtf(var + EPS_);
    }
    __syncthreads();
    float mean = mean_sh, inv = inv_sh;
    float o0 = (v0 - mean) * inv * g[t]       + be[t];
    float o1 = (v1 - mean) * inv * g[t + 256] + be[t + 256];
    out[base + t]       = o0;
    out[base + t + 256] = o1;
    if (outb) {
        outb[base + t]       = __float2bfloat16_rn(o0);
        outb[base + t + 256] = __float2bfloat16_rn(o1);
    }
}

__global__ void __launch_bounds__(256)
ln3_kernel(const float* __restrict__ xb, const float* __restrict__ y,
           const float* __restrict__ gates, const float* __restrict__ b2,
           const float* __restrict__ g, const float* __restrict__ be,
           float* __restrict__ out)
{
    const int row = blockIdx.x;
    const int t = threadIdx.x;
    const size_t base = (size_t)row * D_;
    const float ga0 = gates[(size_t)row * E_ + 0];
    const float ga1 = gates[(size_t)row * E_ + 1];
    const float ga2 = gates[(size_t)row * E_ + 2];
    const float ga3 = gates[(size_t)row * E_ + 3];
    float gb0 = ga0 * b2[t]        + ga1 * b2[D_ + t]        + ga2 * b2[2*D_ + t]        + ga3 * b2[3*D_ + t];
    float gb1 = ga0 * b2[t + 256]  + ga1 * b2[D_ + t + 256]  + ga2 * b2[2*D_ + t + 256]  + ga3 * b2[3*D_ + t + 256];
    float v0 = xb[base + t]       + y[base + t]       + gb0;
    float v1 = xb[base + t + 256] + y[base + t + 256] + gb1;

    float s = v0 + v1, ss = v0 * v0 + v1 * v1;
    const int lane = t & 31, w = t >> 5;
    __shared__ float shs[8], shss[8];
#pragma unroll
    for (int off = 16; off; off >>= 1) {
        s  += __shfl_down_sync(0xffffffffu, s,  off);
        ss += __shfl_down_sync(0xffffffffu, ss, off);
    }
    if (lane == 0) { shs[w] = s; shss[w] = ss; }
    __syncthreads();
    __shared__ float mean_sh, inv_sh;
    if (t == 0) {
        float S = 0.f, SS = 0.f;
#pragma unroll
        for (int i = 0; i < 8; i++) { S += shs[i]; SS += shss[i]; }
        float mean = S * (1.f / (float)D_);
        float var  = SS * (1.f / (float)D_) - mean * mean;
        mean_sh = mean;
        inv_sh  = rsqrtf(var + EPS_);
    }
    __syncthreads();
    float mean = mean_sh, inv = inv_sh;
    out[base + t]       = (v0 - mean) * inv * g[t]       + be[t];
    out[base + t + 256] = (v1 - mean) * inv * g[t + 256] + be[t + 256];
}

// ---------------- gate ----------------
__global__ void __launch_bounds__(256)
gate_kernel(const float* __restrict__ x, const float* __restrict__ gw,
            const float* __restrict__ gb)
{
    const int warp = (blockIdx.x * blockDim.x + threadIdx.x) >> 5;
    const int lane = threadIdx.x & 31;
    if (warp >= BSROWS) return;
    const float* xr = x + (size_t)warp * D_;
    float a0 = 0.f, a1 = 0.f, a2 = 0.f, a3 = 0.f;
    for (int d = lane; d < D_; d += 32) {
        float xv = xr[d];
        const float* wr = gw + (size_t)d * E_;
        a0 += xv * wr[0]; a1 += xv * wr[1]; a2 += xv * wr[2]; a3 += xv * wr[3];
    }
#pragma unroll
    for (int off = 16; off; off >>= 1) {
        a0 += __shfl_down_sync(0xffffffffu, a0, off);
        a1 += __shfl_down_sync(0xffffffffu, a1, off);
        a2 += __shfl_down_sync(0xffffffffu, a2, off);
        a3 += __shfl_down_sync(0xffffffffu, a3, off);
    }
    if (lane == 0) {
        float l0 = a0 + gb[0], l1 = a1 + gb[1], l2 = a2 + gb[2], l3 = a3 + gb[3];
        float mx = fmaxf(fmaxf(l0, l1), fmaxf(l2, l3));
        float e0 = __expf(l0 - mx), e1 = __expf(l1 - mx);
        float e2 = __expf(l2 - mx), e3 = __expf(l3 - mx);
        float si = 1.f / (e0 + e1 + e2 + e3);
        float p0 = e0 * si, p1 = e1 * si, p2 = e2 * si, p3 = e3 * si;
        float* gp = g_gates + (size_t)warp * E_;
        gp[0] = p0; gp[1] = p1; gp[2] = p2; gp[3] = p3;
        atomicAdd(&g_gsum[0], p0);
        atomicAdd(&g_gsum[1], p1);
        atomicAdd(&g_gsum[2], p2);
        atomicAdd(&g_gsum[3], p3);
    }
}

// ---------------- host orchestration ----------------
extern "C" void kernel_launch(void* const* d_in, const int* in_sizes, int n_in,
                              void* d_out, int out_size)
{
    const float* x      = (const float*)d_in[0];
    const float* cross  = (const float*)d_in[1];
    const float* sa_wq  = (const float*)d_in[2];
    const float* sa_bq  = (const float*)d_in[3];
    const float* sa_wk  = (const float*)d_in[4];
    const float* sa_bk  = (const float*)d_in[5];
    const float* sa_wv  = (const float*)d_in[6];
    const float* sa_bv  = (const float*)d_in[7];
    const float* sa_wo  = (const float*)d_in[8];
    const float* sa_bo  = (const float*)d_in[9];
    const float* ca_wq  = (const float*)d_in[10];
    const float* ca_bq  = (const float*)d_in[11];
    const float* ca_wk  = (const float*)d_in[12];
    const float* ca_bk  = (const float*)d_in[13];
    const float* ca_wv  = (const float*)d_in[14];
    const float* ca_bv  = (const float*)d_in[15];
    const float* ca_wo  = (const float*)d_in[16];
    const float* ca_bo  = (const float*)d_in[17];
    const float* gate_w = (const float*)d_in[18];
    const float* gate_b = (const float*)d_in[19];
    const float* exp_w1 = (const float*)d_in[20];
    const float* exp_b1 = (const float*)d_in[21];
    const float* exp_w2 = (const float*)d_in[22];
    const float* exp_b2 = (const float*)d_in[23];
    const float* n1_g   = (const float*)d_in[24];
    const float* n1_b   = (const float*)d_in[25];
    const float* n2_g   = (const float*)d_in[26];
    const float* n2_b   = (const float*)d_in[27];
    const float* n3_g   = (const float*)d_in[28];
    const float* n3_b   = (const float*)d_in[29];
    float* out = (float*)d_out;

    float *qkv, *pre, *xa, *xb, *y, *gates, *bqkv, *bcakv;
    __nv_bfloat16 *attbf, *xabf, *xbbf, *hbf, *xbf, *crbf;
    __nv_bfloat16 *wqkvt, *wsaot, *wcaqt, *wcakvt, *wcaot, *w1t, *w2t;
    cudaGetSymbolAddress((void**)&qkv,    g_qkv);
    cudaGetSymbolAddress((void**)&pre,    g_pre);
    cudaGetSymbolAddress((void**)&xa,     g_xa);
    cudaGetSymbolAddress((void**)&xb,     g_xb);
    cudaGetSymbolAddress((void**)&y,      g_y);
    cudaGetSymbolAddress((void**)&gates,  g_gates);
    cudaGetSymbolAddress((void**)&bqkv,   g_bqkv);
    cudaGetSymbolAddress((void**)&bcakv,  g_bcakv);
    cudaGetSymbolAddress((void**)&attbf,  g_attbf);
    cudaGetSymbolAddress((void**)&xabf,   g_xabf);
    cudaGetSymbolAddress((void**)&xbbf,   g_xbbf);
    cudaGetSymbolAddress((void**)&hbf,    g_hbf);
    cudaGetSymbolAddress((void**)&xbf,    g_xbf);
    cudaGetSymbolAddress((void**)&crbf,   g_crbf);
    cudaGetSymbolAddress((void**)&wqkvt,  g_wqkvt);
    cudaGetSymbolAddress((void**)&wsaot,  g_wsaot);
    cudaGetSymbolAddress((void**)&wcaqt,  g_wcaqt);
    cudaGetSymbolAddress((void**)&wcakvt, g_wcakvt);
    cudaGetSymbolAddress((void**)&wcaot,  g_wcaot);
    cudaGetSymbolAddress((void**)&w1t,    g_w1t);
    cudaGetSymbolAddress((void**)&w2t,    g_w2t);

    static bool attr_done = false;
    if (!attr_done) {
        cudaFuncSetAttribute(fattn_kernel<true>,
                             cudaFuncAttributeMaxDynamicSharedMemorySize, ATTN_SMEM_BYTES);
        cudaFuncSetAttribute(fattn_kernel<false>,
                             cudaFuncAttributeMaxDynamicSharedMemorySize, ATTN_SMEM_BYTES);
        cudaFuncSetAttribute(bgemm_kernel,
                             cudaFuncAttributeMaxDynamicSharedMemorySize, BG_SMEM_BYTES);
        attr_done = true;
    }

    dim3 tb(32, 8);

    // ---- prep ordered so ncu (-s 5 -c 1) captures launch #6 = QKV bgemm ----
    zero_gsum_kernel<<<1, 32>>>();                                           // 1
    cvtbf_kernel<<<(BSROWS*D_/4 + 255)/256, 256>>>(x, xbf, BSROWS*D_/4);     // 2
    cvtbf_kernel<<<(BTROWS*D_/4 + 255)/256, 256>>>(cross, crbf, BTROWS*D_/4);// 3
    tpackz_kernel<<<dim3(16,16,3), tb>>>(sa_wq, sa_wk, sa_wv, wqkvt);        // 4
    pack3f_kernel<<<2, 256>>>(sa_bq, sa_bk, sa_bv, bqkv);                    // 5
    bgemm(xbf, 512, wqkvt, 512, bqkv, nullptr, nullptr, qkv, nullptr, 1536,  // 6 (profiled)
          BSROWS, 1536, FLAG_WF32 | FLAG_WTF32);

    // remaining weight packs (consumed later in the stream)
    tpack3_kernel<<<dim3(16,16,1), tb>>>(sa_wo, 512, 0, wsaot, 512, 0, 0, 0, 0);
    tpack3_kernel<<<dim3(16,16,1), tb>>>(ca_wq, 512, 0, wcaqt, 512, 0, 0, 0, 0);
    tpackz_kernel<<<dim3(16,16,2), tb>>>(ca_wk, ca_wv, nullptr, wcakvt);
    tpack3_kernel<<<dim3(16,16,1), tb>>>(ca_wo, 512, 0, wcaot, 512, 0, 0, 0, 0);
    tpack3_kernel<<<dim3(64,16,4), tb>>>(exp_w1, DF_, (size_t)D_*DF_, w1t, 512, 0, 0, DF_, 0);
    tpack3_kernel<<<dim3(16,64,4), tb>>>(exp_w2, 512, (size_t)DF_*D_, w2t, 8192, 0, 0, 0, DF_);
    pack3f_kernel<<<2, 256>>>(ca_bk, ca_bv, nullptr, bcakv);

    // ---- self-attention block ----
    fattn_kernel<true><<<dim3(S_/64, H_, B_), 128, ATTN_SMEM_BYTES>>>(
        qkv, 1536, qkv + 512, qkv + 1024, 1536, attbf, S_);
    bgemm(attbf, 512, wsaot, 512, sa_bo, /*res=*/x, nullptr, pre, nullptr, 512,
          BSROWS, 512, FLAG_WF32);
    ln_kernel<<<BSROWS, 256>>>(pre, n1_g, n1_b, xa, xabf);

    // ---- cross-attention block ----
    float* qc  = qkv;
    float* kvc = qkv + (size_t)BSROWS * 512;
    bgemm(xabf, 512, wcaqt, 512, ca_bq, nullptr, nullptr, qc, nullptr, 512,
          BSROWS, 512, FLAG_WF32 | FLAG_WTF32);
    bgemm(crbf, 512, wcakvt, 512, bcakv, nullptr, nullptr, kvc, nullptr, 1024,
          BTROWS, 1024, FLAG_WF32 | FLAG_WTF32);
    fattn_kernel<false><<<dim3(S_/64, H_, B_), 128, ATTN_SMEM_BYTES>>>(
        qc, 512, kvc, kvc + 512, 1024, attbf, T_);
    bgemm(attbf, 512, wcaot, 512, ca_bo, /*res=*/xa, nullptr, pre, nullptr, 512,
          BSROWS, 512, FLAG_WF32);
    ln_kernel<<<BSROWS, 256>>>(pre, n2_g, n2_b, xb, xbbf);

    // ---- MoE ----
    gate_kernel<<<(BSROWS * 32 + 255) / 256, 256>>>(xb, gate_w, gate_b);
    aux_kernel<<<1, 1>>>(out, out_size);
    bgemm(xbbf, 512, w1t, 512, exp_b1, nullptr, gates, nullptr, hbf, 8192,
          BSROWS, 8192, FLAG_RELU | FLAG_GATE | FLAG_WBF16);
    bgemm(hbf, 8192, w2t, 8192, nullptr, nullptr, nullptr, y, nullptr, 512,
          BSROWS, 512, FLAG_WF32);
    ln3_kernel<<<BSROWS, 256>>>(xb, y, gates, exp_b2, n3_g, n3_b, out);
}